// round 2
// baseline (speedup 1.0000x reference)
#include <cuda_runtime.h>
#include <cstddef>
#include <cstdint>

#define CDIV(a,b) (((a)+(b)-1)/(b))

constexpr int NU    = 50000;
constexpr int NR    = 20000;
constexpr int DIN   = 512;
constexpr int H     = 256;
constexpr int H4    = H / 4;
constexpr int EREV  = 500000;
constexpr int ENEAR = 250000;

// ---------------- scratch (static device globals; no allocations) ----------
__device__ float g_hu[(size_t)NU * H];
__device__ float g_hr[(size_t)NR * H];
__device__ float g_tuw[(size_t)NU * H];   // hu @ W_ur
__device__ float g_trr[(size_t)NR * H];   // hr @ W_rr
__device__ float g_tru[(size_t)NR * H];   // hr @ W_ru
__device__ float g_accU[(size_t)NU * H];
__device__ float g_accR[(size_t)NR * H];
__device__ float g_nrev[EREV];
__device__ float g_nnear[ENEAR];
__device__ int   g_deg[NU + 3 * NR];
__device__ float g_inv_du[NU];
__device__ float g_inv_dr[NR];
__device__ float g_inv_ds[NR];
__device__ float g_inv_dd[NR];

// ---------------- small kernels --------------------------------------------
__global__ void count_deg(const int* __restrict__ idx, int* __restrict__ deg, int E) {
    int i = blockIdx.x * 256 + threadIdx.x;
    if (i < E) atomicAdd(&deg[idx[i]], 1);
}

__global__ void make_inv(const int* __restrict__ deg, float* __restrict__ inv, int n, int add) {
    int i = blockIdx.x * 256 + threadIdx.x;
    if (i < n) {
        int d = deg[i] + add;
        inv[i] = d > 0 ? rsqrtf((float)d) : 0.f;
    }
}

__global__ void make_norm(const int* __restrict__ s, const int* __restrict__ d,
                          const float* __restrict__ invs, const float* __restrict__ invd,
                          float* __restrict__ nrm, int E) {
    int i = blockIdx.x * 256 + threadIdx.x;
    if (i < E) nrm[i] = invs[s[i]] * invd[d[i]];
}

// ---------------- fp32 SGEMM: C[M x 256] = A[M x K] @ B[K x 256] ------------
// 128x128 block tile, BK=8, 256 threads, 8x8 per-thread microtile.
__global__ __launch_bounds__(256) void sgemm(const float* __restrict__ A,
                                             const float* __restrict__ B,
                                             float* __restrict__ C,
                                             int M, int K) {
    __shared__ float As[8][128];
    __shared__ float Bs[8][128];

    int tid  = threadIdx.x;
    int brow = blockIdx.y * 128;
    int bcol = blockIdx.x * 128;

    int a_row = tid >> 1;          // 0..127
    int a_col = (tid & 1) * 4;     // 0 or 4
    int b_row = tid >> 5;          // 0..7
    int b_col = (tid & 31) * 4;    // 0..124

    int tx = tid & 15;             // 0..15 -> 8 cols each
    int ty = tid >> 4;             // 0..15 -> 8 rows each

    float acc[8][8];
#pragma unroll
    for (int i = 0; i < 8; i++)
#pragma unroll
        for (int j = 0; j < 8; j++) acc[i][j] = 0.f;

    bool a_ok = (brow + a_row) < M;
    const float* Aptr = A + (size_t)(brow + a_row) * K + a_col;
    const float* Bptr = B + (size_t)b_row * 256 + bcol + b_col;

    for (int k0 = 0; k0 < K; k0 += 8) {
        float4 av = a_ok ? *(const float4*)(Aptr + k0) : make_float4(0.f, 0.f, 0.f, 0.f);
        As[a_col + 0][a_row] = av.x;
        As[a_col + 1][a_row] = av.y;
        As[a_col + 2][a_row] = av.z;
        As[a_col + 3][a_row] = av.w;
        float4 bv = *(const float4*)(Bptr + (size_t)k0 * 256);
        *(float4*)&Bs[b_row][b_col] = bv;
        __syncthreads();
#pragma unroll
        for (int kk = 0; kk < 8; kk++) {
            float4 ra0 = *(const float4*)&As[kk][ty * 8];
            float4 ra1 = *(const float4*)&As[kk][ty * 8 + 4];
            float4 rb0 = *(const float4*)&Bs[kk][tx * 8];
            float4 rb1 = *(const float4*)&Bs[kk][tx * 8 + 4];
            float ra[8] = {ra0.x, ra0.y, ra0.z, ra0.w, ra1.x, ra1.y, ra1.z, ra1.w};
            float rb[8] = {rb0.x, rb0.y, rb0.z, rb0.w, rb1.x, rb1.y, rb1.z, rb1.w};
#pragma unroll
            for (int i = 0; i < 8; i++)
#pragma unroll
                for (int j = 0; j < 8; j++)
                    acc[i][j] += ra[i] * rb[j];
        }
        __syncthreads();
    }

#pragma unroll
    for (int i = 0; i < 8; i++) {
        int row = brow + ty * 8 + i;
        if (row < M) {
            float* cp = C + (size_t)row * 256 + bcol + tx * 8;
            *(float4*)(cp)     = make_float4(acc[i][0], acc[i][1], acc[i][2], acc[i][3]);
            *(float4*)(cp + 4) = make_float4(acc[i][4], acc[i][5], acc[i][6], acc[i][7]);
        }
    }
}

// ---------------- aggregation init / scatter / relu -------------------------
// acc[row, :] = b_ur + b_rr + trr[row, :] * inv_ds[row]*inv_dd[row]  (self-loop term)
__global__ void init_rest_acc(const float* __restrict__ trr,
                              const float* __restrict__ bA, const float* __restrict__ bB,
                              float* __restrict__ acc) {
    int i = blockIdx.x * 256 + threadIdx.x;
    if (i >= NR * H4) return;
    int row = i >> 6, c = i & 63;
    float coef = g_inv_ds[row] * g_inv_dd[row];
    float4 t = ((const float4*)trr)[i];
    float4 a = ((const float4*)bA)[c];
    float4 b = ((const float4*)bB)[c];
    ((float4*)acc)[i] = make_float4(a.x + b.x + t.x * coef,
                                    a.y + b.y + t.y * coef,
                                    a.z + b.z + t.z * coef,
                                    a.w + b.w + t.w * coef);
}

__global__ void init_bias(float* __restrict__ acc, const float* __restrict__ b, int n4) {
    int i = blockIdx.x * 256 + threadIdx.x;
    if (i < n4) ((float4*)acc)[i] = ((const float4*)b)[i & 63];
}

// one thread per (edge, 4-float chunk); warp covers 512B of a single src row
__global__ void scatter_add(const float* __restrict__ feat,
                            const int* __restrict__ src, const int* __restrict__ dst,
                            const float* __restrict__ nrm,
                            float* __restrict__ out, int E) {
    int gid = blockIdx.x * 256 + threadIdx.x;
    int e = gid >> 6;
    if (e >= E) return;
    int c = gid & 63;
    int s = __ldg(src + e);
    int d = __ldg(dst + e);
    float n = __ldg(nrm + e);
    float4 v = ((const float4*)(feat + (size_t)s * H))[c];
    float* p = out + (size_t)d * H + c * 4;
    asm volatile("red.global.add.v4.f32 [%0], {%1,%2,%3,%4};"
                 :: "l"(p), "f"(v.x * n), "f"(v.y * n), "f"(v.z * n), "f"(v.w * n)
                 : "memory");
}

__global__ void relu_copy(const float* __restrict__ in, float* __restrict__ out, int n4) {
    int i = blockIdx.x * 256 + threadIdx.x;
    if (i < n4) {
        float4 v = ((const float4*)in)[i];
        ((float4*)out)[i] = make_float4(fmaxf(v.x, 0.f), fmaxf(v.y, 0.f),
                                        fmaxf(v.z, 0.f), fmaxf(v.w, 0.f));
    }
}

// ---------------- host orchestration ----------------------------------------
extern "C" void kernel_launch(void* const* d_in, const int* in_sizes, int n_in,
                              void* d_out, int out_size) {
    const float* x_user    = (const float*)d_in[0];
    const float* x_rest    = (const float*)d_in[1];
    const int*   rev_src   = (const int*)d_in[2];
    const int*   rev_dst   = (const int*)d_in[3];
    const int*   near_src  = (const int*)d_in[4];
    const int*   near_dst  = (const int*)d_in[5];
    const float* Win_user  = (const float*)d_in[6];
    const float* Win_rest  = (const float*)d_in[7];
    const float* W1_ur = (const float*)d_in[8];
    const float* b1_ur = (const float*)d_in[9];
    const float* W1_ru = (const float*)d_in[10];
    const float* b1_ru = (const float*)d_in[11];
    const float* W1_rr = (const float*)d_in[12];
    const float* b1_rr = (const float*)d_in[13];
    const float* W2_ur = (const float*)d_in[14];
    const float* b2_ur = (const float*)d_in[15];
    const float* W2_ru = (const float*)d_in[16];
    const float* b2_ru = (const float*)d_in[17];
    const float* W2_rr = (const float*)d_in[18];
    const float* b2_rr = (const float*)d_in[19];
    const float* Wout_user = (const float*)d_in[20];
    const float* Wout_rest = (const float*)d_in[21];

    float *hu, *hr, *tuw, *trr, *tru, *accU, *accR, *nrev, *nnear;
    float *inv_du, *inv_dr, *inv_ds, *inv_dd;
    int* deg;
    cudaGetSymbolAddress((void**)&hu, g_hu);
    cudaGetSymbolAddress((void**)&hr, g_hr);
    cudaGetSymbolAddress((void**)&tuw, g_tuw);
    cudaGetSymbolAddress((void**)&trr, g_trr);
    cudaGetSymbolAddress((void**)&tru, g_tru);
    cudaGetSymbolAddress((void**)&accU, g_accU);
    cudaGetSymbolAddress((void**)&accR, g_accR);
    cudaGetSymbolAddress((void**)&nrev, g_nrev);
    cudaGetSymbolAddress((void**)&nnear, g_nnear);
    cudaGetSymbolAddress((void**)&inv_du, g_inv_du);
    cudaGetSymbolAddress((void**)&inv_dr, g_inv_dr);
    cudaGetSymbolAddress((void**)&inv_ds, g_inv_ds);
    cudaGetSymbolAddress((void**)&inv_dd, g_inv_dd);
    cudaGetSymbolAddress((void**)&deg, g_deg);

    int* du = deg;
    int* dr = deg + NU;
    int* ds = dr + NR;
    int* dd = ds + NR;

    // degrees + norms (recomputed every call; deterministic)
    cudaMemsetAsync(deg, 0, sizeof(int) * (NU + 3 * NR));
    count_deg<<<CDIV(EREV, 256), 256>>>(rev_src, du, EREV);
    count_deg<<<CDIV(EREV, 256), 256>>>(rev_dst, dr, EREV);
    count_deg<<<CDIV(ENEAR, 256), 256>>>(near_src, ds, ENEAR);
    count_deg<<<CDIV(ENEAR, 256), 256>>>(near_dst, dd, ENEAR);
    make_inv<<<CDIV(NU, 256), 256>>>(du, inv_du, NU, 0);
    make_inv<<<CDIV(NR, 256), 256>>>(dr, inv_dr, NR, 0);
    make_inv<<<CDIV(NR, 256), 256>>>(ds, inv_ds, NR, 1);
    make_inv<<<CDIV(NR, 256), 256>>>(dd, inv_dd, NR, 1);
    make_norm<<<CDIV(EREV, 256), 256>>>(rev_src, rev_dst, inv_du, inv_dr, nrev, EREV);
    make_norm<<<CDIV(ENEAR, 256), 256>>>(near_src, near_dst, inv_ds, inv_dd, nnear, ENEAR);

    dim3 gU(2, CDIV(NU, 128));
    dim3 gR(2, CDIV(NR, 128));

    // input projection
    sgemm<<<gU, 256>>>(x_user, Win_user, hu, NU, DIN);
    sgemm<<<gR, 256>>>(x_rest, Win_rest, hr, NR, DIN);

    // two hetero layers
    const float* Wur[2] = {W1_ur, W2_ur}; const float* bur[2] = {b1_ur, b2_ur};
    const float* Wru[2] = {W1_ru, W2_ru}; const float* bru[2] = {b1_ru, b2_ru};
    const float* Wrr[2] = {W1_rr, W2_rr}; const float* brr[2] = {b1_rr, b2_rr};
    for (int l = 0; l < 2; l++) {
        sgemm<<<gU, 256>>>(hu, Wur[l], tuw, NU, H);
        sgemm<<<gR, 256>>>(hr, Wrr[l], trr, NR, H);
        sgemm<<<gR, 256>>>(hr, Wru[l], tru, NR, H);

        // rest-node accumulator: biases + rr self-loop term, then two scatters
        init_rest_acc<<<CDIV(NR * H4, 256), 256>>>(trr, bur[l], brr[l], accR);
        scatter_add<<<CDIV((size_t)EREV * 64, 256), 256>>>(tuw, rev_src, rev_dst, nrev, accR, EREV);
        scatter_add<<<CDIV((size_t)ENEAR * 64, 256), 256>>>(trr, near_src, near_dst, nnear, accR, ENEAR);

        // user-node accumulator: bias, then reversed rev scatter
        init_bias<<<CDIV(NU * H4, 256), 256>>>(accU, bru[l], NU * H4);
        scatter_add<<<CDIV((size_t)EREV * 64, 256), 256>>>(tru, rev_dst, rev_src, nrev, accU, EREV);

        relu_copy<<<CDIV(NU * H4, 256), 256>>>(accU, hu, NU * H4);
        relu_copy<<<CDIV(NR * H4, 256), 256>>>(accR, hr, NR * H4);
    }

    // output projection straight into d_out: [user block | rest block]
    float* out = (float*)d_out;
    sgemm<<<gU, 256>>>(hu, Wout_user, out, NU, H);
    sgemm<<<gR, 256>>>(hr, Wout_rest, out + (size_t)NU * H, NR, H);
}

// round 4
// speedup vs baseline: 1.3826x; 1.3826x over previous
#include <cuda_runtime.h>
#include <cuda_bf16.h>
#include <mma.h>
#include <cstddef>
#include <cstdint>

using namespace nvcuda;

#define CDIV(a,b) (((a)+(b)-1)/(b))

constexpr int NU    = 50000;
constexpr int NR    = 20000;
constexpr int DIN   = 512;
constexpr int H     = 256;
constexpr int H4    = H / 4;
constexpr int EREV  = 500000;
constexpr int ENEAR = 250000;

// ---------------- scratch (static device globals; no allocations) ----------
__device__ float g_hu[(size_t)NU * H];
__device__ float g_hr[(size_t)NR * H];
__device__ float g_tuw[(size_t)NU * H];
__device__ float g_trr[(size_t)NR * H];
__device__ float g_tru[(size_t)NR * H];
__device__ float g_accU[(size_t)NU * H];
__device__ float g_accR[(size_t)NR * H];
__device__ float g_nrev[EREV];
__device__ float g_nnear[ENEAR];
__device__ int   g_deg[NU + 3 * NR];
__device__ float g_inv_du[NU];
__device__ float g_inv_dr[NR];
__device__ float g_inv_ds[NR];
__device__ float g_inv_dd[NR];

// ---------------- bf16-split wmma GEMM: C[M x 256] = A[M x K] @ W[K x 256] --
// A fp32 row-major, W fp32 row-major [K][256]. Internally each operand is
// split x = hi + lo (both bf16); acc += ah*bh + al*bh + ah*bl  (error ~2^-16).
constexpr int BM = 128, BN = 128, BK = 32;
constexpr int LDA = BK + 8;    // 40 bf16
constexpr int LDB = BN + 8;    // 136 bf16
constexpr int SM_AH = 0;
constexpr int SM_AL = SM_AH + BM * LDA;          // elements (bf16)
constexpr int SM_BH = SM_AL + BM * LDA;
constexpr int SM_BL = SM_BH + BK * LDB;
constexpr int SM_ELEMS = SM_BL + BK * LDB;       // 18944 bf16 = 37888 B

__global__ __launch_bounds__(256) void wgemm(const float* __restrict__ A,
                                             const float* __restrict__ W,
                                             float* __restrict__ C,
                                             int M, int K) {
    extern __shared__ __nv_bfloat16 sm[];
    __nv_bfloat16* Ah = sm + SM_AH;
    __nv_bfloat16* Al = sm + SM_AL;
    __nv_bfloat16* Bh = sm + SM_BH;
    __nv_bfloat16* Bl = sm + SM_BL;

    int tid  = threadIdx.x;
    int wid  = tid >> 5;
    int lane = tid & 31;
    int row0 = blockIdx.y * BM;
    int col0 = blockIdx.x * BN;
    int wm   = wid >> 1;        // 0..3 -> rows wm*32
    int wn   = wid & 1;         // 0..1 -> cols wn*64

    wmma::fragment<wmma::accumulator, 16, 16, 16, float> acc[2][4];
#pragma unroll
    for (int mi = 0; mi < 2; mi++)
#pragma unroll
        for (int ni = 0; ni < 4; ni++) wmma::fill_fragment(acc[mi][ni], 0.f);

    for (int k0 = 0; k0 < K; k0 += BK) {
        // A tile: 128x32 fp32 -> hi/lo bf16. 1024 float4 / 256 thr = 4 each.
#pragma unroll
        for (int q = 0; q < 4; q++) {
            int i   = tid + 256 * q;
            int row = i >> 3;
            int c4  = (i & 7) << 2;
            float4 v = (row0 + row < M)
                ? *(const float4*)(A + (size_t)(row0 + row) * K + k0 + c4)
                : make_float4(0.f, 0.f, 0.f, 0.f);
            float vv[4] = {v.x, v.y, v.z, v.w};
            __nv_bfloat16* ph = Ah + row * LDA + c4;
            __nv_bfloat16* pl = Al + row * LDA + c4;
#pragma unroll
            for (int j = 0; j < 4; j++) {
                __nv_bfloat16 h = __float2bfloat16_rn(vv[j]);
                ph[j] = h;
                pl[j] = __float2bfloat16_rn(vv[j] - __bfloat162float(h));
            }
        }
        // B tile: 32x128 fp32 (rows = k, cols = n) -> hi/lo bf16.
#pragma unroll
        for (int q = 0; q < 4; q++) {
            int i   = tid + 256 * q;
            int kk  = i >> 5;
            int c4  = (i & 31) << 2;
            float4 v = *(const float4*)(W + (size_t)(k0 + kk) * 256 + col0 + c4);
            float vv[4] = {v.x, v.y, v.z, v.w};
            __nv_bfloat16* ph = Bh + kk * LDB + c4;
            __nv_bfloat16* pl = Bl + kk * LDB + c4;
#pragma unroll
            for (int j = 0; j < 4; j++) {
                __nv_bfloat16 h = __float2bfloat16_rn(vv[j]);
                ph[j] = h;
                pl[j] = __float2bfloat16_rn(vv[j] - __bfloat162float(h));
            }
        }
        __syncthreads();

#pragma unroll
        for (int kk = 0; kk < BK; kk += 16) {
            wmma::fragment<wmma::matrix_a, 16, 16, 16, __nv_bfloat16, wmma::row_major> ah[2], al[2];
#pragma unroll
            for (int mi = 0; mi < 2; mi++) {
                const __nv_bfloat16* ap = Ah + (wm * 32 + mi * 16) * LDA + kk;
                const __nv_bfloat16* lp = Al + (wm * 32 + mi * 16) * LDA + kk;
                wmma::load_matrix_sync(ah[mi], ap, LDA);
                wmma::load_matrix_sync(al[mi], lp, LDA);
            }
#pragma unroll
            for (int ni = 0; ni < 4; ni++) {
                wmma::fragment<wmma::matrix_b, 16, 16, 16, __nv_bfloat16, wmma::row_major> bh, bl;
                const __nv_bfloat16* bp = Bh + kk * LDB + wn * 64 + ni * 16;
                const __nv_bfloat16* qp = Bl + kk * LDB + wn * 64 + ni * 16;
                wmma::load_matrix_sync(bh, bp, LDB);
                wmma::load_matrix_sync(bl, qp, LDB);
#pragma unroll
                for (int mi = 0; mi < 2; mi++) {
                    wmma::mma_sync(acc[mi][ni], ah[mi], bh, acc[mi][ni]);
                    wmma::mma_sync(acc[mi][ni], al[mi], bh, acc[mi][ni]);
                    wmma::mma_sync(acc[mi][ni], ah[mi], bl, acc[mi][ni]);
                }
            }
        }
        __syncthreads();
    }

    // epilogue
    if (row0 + BM <= M) {
#pragma unroll
        for (int mi = 0; mi < 2; mi++)
#pragma unroll
            for (int ni = 0; ni < 4; ni++) {
                float* cp = C + (size_t)(row0 + wm * 32 + mi * 16) * 256
                              + col0 + wn * 64 + ni * 16;
                wmma::store_matrix_sync(cp, acc[mi][ni], 256, wmma::mem_row_major);
            }
    } else {
        // boundary block: stage per-fragment through smem with row guards
        __syncthreads();                    // smem tiles are dead; reuse
        float* stage = (float*)sm + wid * 416;   // 16 rows x 24 cols per warp
#pragma unroll
        for (int mi = 0; mi < 2; mi++)
#pragma unroll
            for (int ni = 0; ni < 4; ni++) {
                wmma::store_matrix_sync(stage, acc[mi][ni], 24, wmma::mem_row_major);
                __syncwarp();
#pragma unroll
                for (int j = 0; j < 8; j++) {
                    int e   = lane * 8 + j;
                    int r   = e >> 4, cc = e & 15;
                    int row = row0 + wm * 32 + mi * 16 + r;
                    if (row < M)
                        C[(size_t)row * 256 + col0 + wn * 64 + ni * 16 + cc] =
                            stage[r * 24 + cc];
                }
                __syncwarp();
            }
    }
}

// ---------------- small kernels --------------------------------------------
__global__ void count_deg(const int* __restrict__ idx, int* __restrict__ deg, int E) {
    int i = blockIdx.x * 256 + threadIdx.x;
    if (i < E) atomicAdd(&deg[idx[i]], 1);
}

__global__ void make_inv(const int* __restrict__ deg, float* __restrict__ inv, int n, int add) {
    int i = blockIdx.x * 256 + threadIdx.x;
    if (i < n) {
        int d = deg[i] + add;
        inv[i] = d > 0 ? rsqrtf((float)d) : 0.f;
    }
}

__global__ void make_norm(const int* __restrict__ s, const int* __restrict__ d,
                          const float* __restrict__ invs, const float* __restrict__ invd,
                          float* __restrict__ nrm, int E) {
    int i = blockIdx.x * 256 + threadIdx.x;
    if (i < E) nrm[i] = invs[s[i]] * invd[d[i]];
}

__global__ void init_rest_acc(const float* __restrict__ trr,
                              const float* __restrict__ bA, const float* __restrict__ bB,
                              float* __restrict__ acc) {
    int i = blockIdx.x * 256 + threadIdx.x;
    if (i >= NR * H4) return;
    int row = i >> 6, c = i & 63;
    float coef = g_inv_ds[row] * g_inv_dd[row];
    float4 t = ((const float4*)trr)[i];
    float4 a = ((const float4*)bA)[c];
    float4 b = ((const float4*)bB)[c];
    ((float4*)acc)[i] = make_float4(a.x + b.x + t.x * coef,
                                    a.y + b.y + t.y * coef,
                                    a.z + b.z + t.z * coef,
                                    a.w + b.w + t.w * coef);
}

__global__ void init_bias(float* __restrict__ acc, const float* __restrict__ b, int n4) {
    int i = blockIdx.x * 256 + threadIdx.x;
    if (i < n4) ((float4*)acc)[i] = ((const float4*)b)[i & 63];
}

__global__ void scatter_add(const float* __restrict__ feat,
                            const int* __restrict__ src, const int* __restrict__ dst,
                            const float* __restrict__ nrm,
                            float* __restrict__ out, int E) {
    int gid = blockIdx.x * 256 + threadIdx.x;
    int e = gid >> 6;
    if (e >= E) return;
    int c = gid & 63;
    int s = __ldg(src + e);
    int d = __ldg(dst + e);
    float n = __ldg(nrm + e);
    float4 v = ((const float4*)(feat + (size_t)s * H))[c];
    float* p = out + (size_t)d * H + c * 4;
    asm volatile("red.global.add.v4.f32 [%0], {%1,%2,%3,%4};"
                 :: "l"(p), "f"(v.x * n), "f"(v.y * n), "f"(v.z * n), "f"(v.w * n)
                 : "memory");
}

__global__ void relu_copy(const float* __restrict__ in, float* __restrict__ out, int n4) {
    int i = blockIdx.x * 256 + threadIdx.x;
    if (i < n4) {
        float4 v = ((const float4*)in)[i];
        ((float4*)out)[i] = make_float4(fmaxf(v.x, 0.f), fmaxf(v.y, 0.f),
                                        fmaxf(v.z, 0.f), fmaxf(v.w, 0.f));
    }
}

// ---------------- host orchestration ----------------------------------------
extern "C" void kernel_launch(void* const* d_in, const int* in_sizes, int n_in,
                              void* d_out, int out_size) {
    const float* x_user    = (const float*)d_in[0];
    const float* x_rest    = (const float*)d_in[1];
    const int*   rev_src   = (const int*)d_in[2];
    const int*   rev_dst   = (const int*)d_in[3];
    const int*   near_src  = (const int*)d_in[4];
    const int*   near_dst  = (const int*)d_in[5];
    const float* Win_user  = (const float*)d_in[6];
    const float* Win_rest  = (const float*)d_in[7];
    const float* W1_ur = (const float*)d_in[8];
    const float* b1_ur = (const float*)d_in[9];
    const float* W1_ru = (const float*)d_in[10];
    const float* b1_ru = (const float*)d_in[11];
    const float* W1_rr = (const float*)d_in[12];
    const float* b1_rr = (const float*)d_in[13];
    const float* W2_ur = (const float*)d_in[14];
    const float* b2_ur = (const float*)d_in[15];
    const float* W2_ru = (const float*)d_in[16];
    const float* b2_ru = (const float*)d_in[17];
    const float* W2_rr = (const float*)d_in[18];
    const float* b2_rr = (const float*)d_in[19];
    const float* Wout_user = (const float*)d_in[20];
    const float* Wout_rest = (const float*)d_in[21];

    float *hu, *hr, *tuw, *trr, *tru, *accU, *accR, *nrev, *nnear;
    float *inv_du, *inv_dr, *inv_ds, *inv_dd;
    int* deg;
    cudaGetSymbolAddress((void**)&hu, g_hu);
    cudaGetSymbolAddress((void**)&hr, g_hr);
    cudaGetSymbolAddress((void**)&tuw, g_tuw);
    cudaGetSymbolAddress((void**)&trr, g_trr);
    cudaGetSymbolAddress((void**)&tru, g_tru);
    cudaGetSymbolAddress((void**)&accU, g_accU);
    cudaGetSymbolAddress((void**)&accR, g_accR);
    cudaGetSymbolAddress((void**)&nrev, g_nrev);
    cudaGetSymbolAddress((void**)&nnear, g_nnear);
    cudaGetSymbolAddress((void**)&inv_du, g_inv_du);
    cudaGetSymbolAddress((void**)&inv_dr, g_inv_dr);
    cudaGetSymbolAddress((void**)&inv_ds, g_inv_ds);
    cudaGetSymbolAddress((void**)&inv_dd, g_inv_dd);
    cudaGetSymbolAddress((void**)&deg, g_deg);

    int* du = deg;
    int* dr = deg + NU;
    int* ds = dr + NR;
    int* dd = ds + NR;

    cudaMemsetAsync(deg, 0, sizeof(int) * (NU + 3 * NR));
    count_deg<<<CDIV(EREV, 256), 256>>>(rev_src, du, EREV);
    count_deg<<<CDIV(EREV, 256), 256>>>(rev_dst, dr, EREV);
    count_deg<<<CDIV(ENEAR, 256), 256>>>(near_src, ds, ENEAR);
    count_deg<<<CDIV(ENEAR, 256), 256>>>(near_dst, dd, ENEAR);
    make_inv<<<CDIV(NU, 256), 256>>>(du, inv_du, NU, 0);
    make_inv<<<CDIV(NR, 256), 256>>>(dr, inv_dr, NR, 0);
    make_inv<<<CDIV(NR, 256), 256>>>(ds, inv_ds, NR, 1);
    make_inv<<<CDIV(NR, 256), 256>>>(dd, inv_dd, NR, 1);
    make_norm<<<CDIV(EREV, 256), 256>>>(rev_src, rev_dst, inv_du, inv_dr, nrev, EREV);
    make_norm<<<CDIV(ENEAR, 256), 256>>>(near_src, near_dst, inv_ds, inv_dd, nnear, ENEAR);

    const int SMEM = SM_ELEMS * (int)sizeof(__nv_bfloat16);   // 37,888 B
    dim3 gU(2, CDIV(NU, BM));
    dim3 gR(2, CDIV(NR, BM));

    // input projection (K = 512)
    wgemm<<<gU, 256, SMEM>>>(x_user, Win_user, hu, NU, DIN);
    wgemm<<<gR, 256, SMEM>>>(x_rest, Win_rest, hr, NR, DIN);

    const float* Wur[2] = {W1_ur, W2_ur}; const float* bur[2] = {b1_ur, b2_ur};
    const float* Wru[2] = {W1_ru, W2_ru}; const float* bru[2] = {b1_ru, b2_ru};
    const float* Wrr[2] = {W1_rr, W2_rr}; const float* brr[2] = {b1_rr, b2_rr};
    for (int l = 0; l < 2; l++) {
        wgemm<<<gU, 256, SMEM>>>(hu, Wur[l], tuw, NU, H);
        wgemm<<<gR, 256, SMEM>>>(hr, Wrr[l], trr, NR, H);
        wgemm<<<gR, 256, SMEM>>>(hr, Wru[l], tru, NR, H);

        init_rest_acc<<<CDIV(NR * H4, 256), 256>>>(trr, bur[l], brr[l], accR);
        scatter_add<<<CDIV((size_t)EREV * 64, 256), 256>>>(tuw, rev_src, rev_dst, nrev, accR, EREV);
        scatter_add<<<CDIV((size_t)ENEAR * 64, 256), 256>>>(trr, near_src, near_dst, nnear, accR, ENEAR);

        init_bias<<<CDIV(NU * H4, 256), 256>>>(accU, bru[l], NU * H4);
        scatter_add<<<CDIV((size_t)EREV * 64, 256), 256>>>(tru, rev_dst, rev_src, nrev, accU, EREV);

        relu_copy<<<CDIV(NU * H4, 256), 256>>>(accU, hu, NU * H4);
        relu_copy<<<CDIV(NR * H4, 256), 256>>>(accR, hr, NR * H4);
    }

    float* out = (float*)d_out;
    wgemm<<<gU, 256, SMEM>>>(hu, Wout_user, out, NU, H);
    wgemm<<<gR, 256, SMEM>>>(hr, Wout_rest, out + (size_t)NU * H, NR, H);
}

// round 5
// speedup vs baseline: 1.4796x; 1.0701x over previous
#include <cuda_runtime.h>
#include <cuda_bf16.h>
#include <mma.h>
#include <cstddef>
#include <cstdint>

using namespace nvcuda;

#define CDIV(a,b) (((a)+(b)-1)/(b))

constexpr int NU    = 50000;
constexpr int NR    = 20000;
constexpr int DIN   = 512;
constexpr int H     = 256;
constexpr int H4    = H / 4;
constexpr int EREV  = 500000;
constexpr int ENEAR = 250000;

// ---------------- scratch (static device globals; no allocations) ----------
__device__ float g_tuw[(size_t)NU * H];
__device__ float g_trr[(size_t)NR * H];
__device__ float g_tru[(size_t)NR * H];
__device__ float g_accU[(size_t)NU * H];
__device__ float g_accR[(size_t)NR * H];
__device__ float g_nrev[EREV];
__device__ float g_nnear[ENEAR];
__device__ int   g_deg[NU + 3 * NR];
__device__ float g_inv_du[NU];
__device__ float g_inv_dr[NR];
__device__ float g_inv_ds[NR];
__device__ float g_inv_dd[NR];
// bf16 hi/lo operand storage
__device__ __nv_bfloat16 g_xuh[(size_t)NU * DIN], g_xul[(size_t)NU * DIN];
__device__ __nv_bfloat16 g_xrh[(size_t)NR * DIN], g_xrl[(size_t)NR * DIN];
__device__ __nv_bfloat16 g_huh[(size_t)NU * H],   g_hul[(size_t)NU * H];
__device__ __nv_bfloat16 g_hrh[(size_t)NR * H],   g_hrl[(size_t)NR * H];
constexpr int WTOT = 2 * DIN * H + 8 * H * H;   // 786432
__device__ __nv_bfloat16 g_wh[WTOT], g_wl[WTOT];

// ---------------- helpers ----------------------------------------------------
__device__ __forceinline__ uint32_t smem_u32(const void* p) {
    uint32_t a;
    asm("{ .reg .u64 t; cvta.to.shared.u64 t, %1; cvt.u32.u64 %0, t; }" : "=r"(a) : "l"(p));
    return a;
}
__device__ __forceinline__ void cp16(uint32_t dst, const void* src, bool ok) {
    int sz = ok ? 16 : 0;
    asm volatile("cp.async.cg.shared.global [%0], [%1], 16, %2;"
                 :: "r"(dst), "l"(src), "r"(sz) : "memory");
}
#define CP_COMMIT() asm volatile("cp.async.commit_group;" ::: "memory")
#define CP_WAIT1()  asm volatile("cp.async.wait_group 1;" ::: "memory")
#define CP_WAIT0()  asm volatile("cp.async.wait_group 0;" ::: "memory")

// ---------------- split / relu kernels --------------------------------------
__global__ void split_bf16(const float* __restrict__ in,
                           __nv_bfloat16* __restrict__ h,
                           __nv_bfloat16* __restrict__ l, int n4) {
    int i = blockIdx.x * 256 + threadIdx.x;
    if (i >= n4) return;
    float4 v = ((const float4*)in)[i];
    float vv[4] = {v.x, v.y, v.z, v.w};
    __nv_bfloat16 hh[4], ll[4];
#pragma unroll
    for (int j = 0; j < 4; j++) {
        hh[j] = __float2bfloat16_rn(vv[j]);
        ll[j] = __float2bfloat16_rn(vv[j] - __bfloat162float(hh[j]));
    }
    __nv_bfloat162* H2 = (__nv_bfloat162*)(h + (size_t)i * 4);
    __nv_bfloat162* L2 = (__nv_bfloat162*)(l + (size_t)i * 4);
    H2[0] = __halves2bfloat162(hh[0], hh[1]);
    H2[1] = __halves2bfloat162(hh[2], hh[3]);
    L2[0] = __halves2bfloat162(ll[0], ll[1]);
    L2[1] = __halves2bfloat162(ll[2], ll[3]);
}

__global__ void relu_split(const float* __restrict__ in,
                           __nv_bfloat16* __restrict__ h,
                           __nv_bfloat16* __restrict__ l, int n4) {
    int i = blockIdx.x * 256 + threadIdx.x;
    if (i >= n4) return;
    float4 v = ((const float4*)in)[i];
    float vv[4] = {fmaxf(v.x, 0.f), fmaxf(v.y, 0.f), fmaxf(v.z, 0.f), fmaxf(v.w, 0.f)};
    __nv_bfloat16 hh[4], ll[4];
#pragma unroll
    for (int j = 0; j < 4; j++) {
        hh[j] = __float2bfloat16_rn(vv[j]);
        ll[j] = __float2bfloat16_rn(vv[j] - __bfloat162float(hh[j]));
    }
    __nv_bfloat162* H2 = (__nv_bfloat162*)(h + (size_t)i * 4);
    __nv_bfloat162* L2 = (__nv_bfloat162*)(l + (size_t)i * 4);
    H2[0] = __halves2bfloat162(hh[0], hh[1]);
    H2[1] = __halves2bfloat162(hh[2], hh[3]);
    L2[0] = __halves2bfloat162(ll[0], ll[1]);
    L2[1] = __halves2bfloat162(ll[2], ll[3]);
}

// ---------------- double-buffered bf16-split wmma GEMM ----------------------
// C[M x 256] = (Ah+Al)[M x K] @ (Bh+Bl)[K x 256], 3-term products, fp32 acc.
constexpr int BM = 128, BN = 128, BK = 32;
constexpr int LDA = BK + 8;    // 40
constexpr int LDB = BN + 8;    // 136
constexpr int E_AH = 0;
constexpr int E_AL = E_AH + BM * LDA;     // 5120
constexpr int E_BH = E_AL + BM * LDA;     // 10240
constexpr int E_BL = E_BH + BK * LDB;     // 14592
constexpr int STAGE_E = E_BL + BK * LDB;  // 18944 elems = 37888 B
constexpr int GEMM_SMEM = 2 * STAGE_E * 2;  // 75776 B

__global__ __launch_bounds__(256) void wgemm2(const __nv_bfloat16* __restrict__ Ahg,
                                              const __nv_bfloat16* __restrict__ Alg,
                                              const __nv_bfloat16* __restrict__ Bhg,
                                              const __nv_bfloat16* __restrict__ Blg,
                                              float* __restrict__ C, int M, int K) {
    extern __shared__ __nv_bfloat16 sm[];
    uint32_t sbase = smem_u32(sm);

    int tid  = threadIdx.x;
    int wid  = tid >> 5;
    int lane = tid & 31;
    int row0 = blockIdx.y * BM;
    int col0 = blockIdx.x * BN;
    int wm   = wid >> 1;
    int wn   = wid & 1;

    wmma::fragment<wmma::accumulator, 16, 16, 16, float> acc[2][4];
#pragma unroll
    for (int mi = 0; mi < 2; mi++)
#pragma unroll
        for (int ni = 0; ni < 4; ni++) wmma::fill_fragment(acc[mi][ni], 0.f);

    auto load_stage = [&](int st, int k0) {
        uint32_t base = sbase + st * (STAGE_E * 2);
#pragma unroll
        for (int q = 0; q < 2; q++) {
            int i   = tid + 256 * q;          // 0..511
            int row = i >> 2;
            int c8  = (i & 3) << 3;
            bool ok = (row0 + row) < M;
            size_t off = (size_t)(ok ? row0 + row : 0) * K + k0 + c8;
            uint32_t d = base + (row * LDA + c8) * 2;
            cp16(d, Ahg + off, ok);
            cp16(d + E_AL * 2, Alg + off, ok);
        }
#pragma unroll
        for (int q = 0; q < 2; q++) {
            int i  = tid + 256 * q;
            int kk = i >> 4;
            int c8 = (i & 15) << 3;
            size_t off = (size_t)(k0 + kk) * 256 + col0 + c8;
            uint32_t d = base + E_BH * 2 + (kk * LDB + c8) * 2;
            cp16(d, Bhg + off, true);
            cp16(d + (E_BL - E_BH) * 2, Blg + off, true);
        }
    };

    int NC = K / BK;
    load_stage(0, 0);
    CP_COMMIT();

    for (int c = 0; c < NC; c++) {
        if (c + 1 < NC) load_stage((c + 1) & 1, (c + 1) * BK);
        CP_COMMIT();
        CP_WAIT1();
        __syncthreads();

        const __nv_bfloat16* sAh = sm + (c & 1) * STAGE_E + E_AH;
        const __nv_bfloat16* sAl = sm + (c & 1) * STAGE_E + E_AL;
        const __nv_bfloat16* sBh = sm + (c & 1) * STAGE_E + E_BH;
        const __nv_bfloat16* sBl = sm + (c & 1) * STAGE_E + E_BL;

#pragma unroll
        for (int kk = 0; kk < BK; kk += 16) {
            wmma::fragment<wmma::matrix_a, 16, 16, 16, __nv_bfloat16, wmma::row_major> ah[2], al[2];
#pragma unroll
            for (int mi = 0; mi < 2; mi++) {
                wmma::load_matrix_sync(ah[mi], sAh + (wm * 32 + mi * 16) * LDA + kk, LDA);
                wmma::load_matrix_sync(al[mi], sAl + (wm * 32 + mi * 16) * LDA + kk, LDA);
            }
#pragma unroll
            for (int ni = 0; ni < 4; ni++) {
                wmma::fragment<wmma::matrix_b, 16, 16, 16, __nv_bfloat16, wmma::row_major> bh, bl;
                wmma::load_matrix_sync(bh, sBh + kk * LDB + wn * 64 + ni * 16, LDB);
                wmma::load_matrix_sync(bl, sBl + kk * LDB + wn * 64 + ni * 16, LDB);
#pragma unroll
                for (int mi = 0; mi < 2; mi++) {
                    wmma::mma_sync(acc[mi][ni], ah[mi], bh, acc[mi][ni]);
                    wmma::mma_sync(acc[mi][ni], al[mi], bh, acc[mi][ni]);
                    wmma::mma_sync(acc[mi][ni], ah[mi], bl, acc[mi][ni]);
                }
            }
        }
        __syncthreads();
    }

    if (row0 + BM <= M) {
#pragma unroll
        for (int mi = 0; mi < 2; mi++)
#pragma unroll
            for (int ni = 0; ni < 4; ni++) {
                float* cp = C + (size_t)(row0 + wm * 32 + mi * 16) * 256
                              + col0 + wn * 64 + ni * 16;
                wmma::store_matrix_sync(cp, acc[mi][ni], 256, wmma::mem_row_major);
            }
    } else {
        CP_WAIT0();
        __syncthreads();
        float* stage = (float*)sm + wid * 416;
#pragma unroll
        for (int mi = 0; mi < 2; mi++)
#pragma unroll
            for (int ni = 0; ni < 4; ni++) {
                wmma::store_matrix_sync(stage, acc[mi][ni], 24, wmma::mem_row_major);
                __syncwarp();
#pragma unroll
                for (int j = 0; j < 8; j++) {
                    int e   = lane * 8 + j;
                    int r   = e >> 4, cc = e & 15;
                    int row = row0 + wm * 32 + mi * 16 + r;
                    if (row < M)
                        C[(size_t)row * 256 + col0 + wn * 64 + ni * 16 + cc] =
                            stage[r * 24 + cc];
                }
                __syncwarp();
            }
    }
}

// ---------------- graph kernels ---------------------------------------------
__global__ void count_deg(const int* __restrict__ idx, int* __restrict__ deg, int E) {
    int i = blockIdx.x * 256 + threadIdx.x;
    if (i < E) atomicAdd(&deg[idx[i]], 1);
}

__global__ void make_inv(const int* __restrict__ deg, float* __restrict__ inv, int n, int add) {
    int i = blockIdx.x * 256 + threadIdx.x;
    if (i < n) {
        int d = deg[i] + add;
        inv[i] = d > 0 ? rsqrtf((float)d) : 0.f;
    }
}

__global__ void make_norm(const int* __restrict__ s, const int* __restrict__ d,
                          const float* __restrict__ invs, const float* __restrict__ invd,
                          float* __restrict__ nrm, int E) {
    int i = blockIdx.x * 256 + threadIdx.x;
    if (i < E) nrm[i] = invs[s[i]] * invd[d[i]];
}

__global__ void init_rest_acc(const float* __restrict__ trr,
                              const float* __restrict__ bA, const float* __restrict__ bB,
                              float* __restrict__ acc) {
    int i = blockIdx.x * 256 + threadIdx.x;
    if (i >= NR * H4) return;
    int row = i >> 6, c = i & 63;
    float coef = g_inv_ds[row] * g_inv_dd[row];
    float4 t = ((const float4*)trr)[i];
    float4 a = ((const float4*)bA)[c];
    float4 b = ((const float4*)bB)[c];
    ((float4*)acc)[i] = make_float4(a.x + b.x + t.x * coef,
                                    a.y + b.y + t.y * coef,
                                    a.z + b.z + t.z * coef,
                                    a.w + b.w + t.w * coef);
}

__global__ void init_bias(float* __restrict__ acc, const float* __restrict__ b, int n4) {
    int i = blockIdx.x * 256 + threadIdx.x;
    if (i < n4) ((float4*)acc)[i] = ((const float4*)b)[i & 63];
}

__global__ void scatter_add(const float* __restrict__ feat,
                            const int* __restrict__ src, const int* __restrict__ dst,
                            const float* __restrict__ nrm,
                            float* __restrict__ out, int E) {
    int gid = blockIdx.x * 256 + threadIdx.x;
    int e = gid >> 6;
    if (e >= E) return;
    int c = gid & 63;
    int s = __ldg(src + e);
    int d = __ldg(dst + e);
    float n = __ldg(nrm + e);
    float4 v = ((const float4*)(feat + (size_t)s * H))[c];
    float* p = out + (size_t)d * H + c * 4;
    asm volatile("red.global.add.v4.f32 [%0], {%1,%2,%3,%4};"
                 :: "l"(p), "f"(v.x * n), "f"(v.y * n), "f"(v.z * n), "f"(v.w * n)
                 : "memory");
}

// ---------------- host orchestration ----------------------------------------
extern "C" void kernel_launch(void* const* d_in, const int* in_sizes, int n_in,
                              void* d_out, int out_size) {
    const float* x_user    = (const float*)d_in[0];
    const float* x_rest    = (const float*)d_in[1];
    const int*   rev_src   = (const int*)d_in[2];
    const int*   rev_dst   = (const int*)d_in[3];
    const int*   near_src  = (const int*)d_in[4];
    const int*   near_dst  = (const int*)d_in[5];
    const float* Win_user  = (const float*)d_in[6];
    const float* Win_rest  = (const float*)d_in[7];
    const float* W1_ur = (const float*)d_in[8];
    const float* b1_ur = (const float*)d_in[9];
    const float* W1_ru = (const float*)d_in[10];
    const float* b1_ru = (const float*)d_in[11];
    const float* W1_rr = (const float*)d_in[12];
    const float* b1_rr = (const float*)d_in[13];
    const float* W2_ur = (const float*)d_in[14];
    const float* b2_ur = (const float*)d_in[15];
    const float* W2_ru = (const float*)d_in[16];
    const float* b2_ru = (const float*)d_in[17];
    const float* W2_rr = (const float*)d_in[18];
    const float* b2_rr = (const float*)d_in[19];
    const float* Wout_user = (const float*)d_in[20];
    const float* Wout_rest = (const float*)d_in[21];

    cudaFuncSetAttribute(wgemm2, cudaFuncAttributeMaxDynamicSharedMemorySize, GEMM_SMEM);

    float *tuw, *trr, *tru, *accU, *accR, *nrev, *nnear;
    float *inv_du, *inv_dr, *inv_ds, *inv_dd;
    int* deg;
    __nv_bfloat16 *xuh, *xul, *xrh, *xrl, *huh, *hul, *hrh, *hrl, *wh, *wl;
    cudaGetSymbolAddress((void**)&tuw, g_tuw);
    cudaGetSymbolAddress((void**)&trr, g_trr);
    cudaGetSymbolAddress((void**)&tru, g_tru);
    cudaGetSymbolAddress((void**)&accU, g_accU);
    cudaGetSymbolAddress((void**)&accR, g_accR);
    cudaGetSymbolAddress((void**)&nrev, g_nrev);
    cudaGetSymbolAddress((void**)&nnear, g_nnear);
    cudaGetSymbolAddress((void**)&inv_du, g_inv_du);
    cudaGetSymbolAddress((void**)&inv_dr, g_inv_dr);
    cudaGetSymbolAddress((void**)&inv_ds, g_inv_ds);
    cudaGetSymbolAddress((void**)&inv_dd, g_inv_dd);
    cudaGetSymbolAddress((void**)&deg, g_deg);
    cudaGetSymbolAddress((void**)&xuh, g_xuh);
    cudaGetSymbolAddress((void**)&xul, g_xul);
    cudaGetSymbolAddress((void**)&xrh, g_xrh);
    cudaGetSymbolAddress((void**)&xrl, g_xrl);
    cudaGetSymbolAddress((void**)&huh, g_huh);
    cudaGetSymbolAddress((void**)&hul, g_hul);
    cudaGetSymbolAddress((void**)&hrh, g_hrh);
    cudaGetSymbolAddress((void**)&hrl, g_hrl);
    cudaGetSymbolAddress((void**)&wh, g_wh);
    cudaGetSymbolAddress((void**)&wl, g_wl);

    int* du = deg;
    int* dr = deg + NU;
    int* ds = dr + NR;
    int* dd = ds + NR;

    // ---- degrees + norms
    cudaMemsetAsync(deg, 0, sizeof(int) * (NU + 3 * NR));
    count_deg<<<CDIV(EREV, 256), 256>>>(rev_src, du, EREV);
    count_deg<<<CDIV(EREV, 256), 256>>>(rev_dst, dr, EREV);
    count_deg<<<CDIV(ENEAR, 256), 256>>>(near_src, ds, ENEAR);
    count_deg<<<CDIV(ENEAR, 256), 256>>>(near_dst, dd, ENEAR);
    make_inv<<<CDIV(NU, 256), 256>>>(du, inv_du, NU, 0);
    make_inv<<<CDIV(NR, 256), 256>>>(dr, inv_dr, NR, 0);
    make_inv<<<CDIV(NR, 256), 256>>>(ds, inv_ds, NR, 1);
    make_inv<<<CDIV(NR, 256), 256>>>(dd, inv_dd, NR, 1);
    make_norm<<<CDIV(EREV, 256), 256>>>(rev_src, rev_dst, inv_du, inv_dr, nrev, EREV);
    make_norm<<<CDIV(ENEAR, 256), 256>>>(near_src, near_dst, inv_ds, inv_dd, nnear, ENEAR);

    // ---- operand splits (weights + inputs)
    // weight scratch offsets (elems)
    const int O_WIN_U = 0;
    const int O_WIN_R = DIN * H;                 // 131072
    const int O_L[8]  = {2*DIN*H,           2*DIN*H +   H*H, 2*DIN*H + 2*H*H,
                         2*DIN*H + 3*H*H,   2*DIN*H + 4*H*H, 2*DIN*H + 5*H*H,
                         2*DIN*H + 6*H*H,   2*DIN*H + 7*H*H};
    const float* wsrc[8] = {W1_ur, W1_ru, W1_rr, W2_ur, W2_ru, W2_rr, Wout_user, Wout_rest};
    split_bf16<<<CDIV(DIN*H/4, 256), 256>>>(Win_user, wh + O_WIN_U, wl + O_WIN_U, DIN*H/4);
    split_bf16<<<CDIV(DIN*H/4, 256), 256>>>(Win_rest, wh + O_WIN_R, wl + O_WIN_R, DIN*H/4);
    for (int i = 0; i < 8; i++)
        split_bf16<<<CDIV(H*H/4, 256), 256>>>(wsrc[i], wh + O_L[i], wl + O_L[i], H*H/4);
    split_bf16<<<CDIV(NU*DIN/4, 256), 256>>>(x_user, xuh, xul, NU*DIN/4);
    split_bf16<<<CDIV(NR*DIN/4, 256), 256>>>(x_rest, xrh, xrl, NR*DIN/4);

    dim3 gU(2, CDIV(NU, BM));
    dim3 gR(2, CDIV(NR, BM));

    // ---- input projection (K=512) -> f32 temp -> split (no relu on input proj)
    wgemm2<<<gU, 256, GEMM_SMEM>>>(xuh, xul, wh + O_WIN_U, wl + O_WIN_U, tuw, NU, DIN);
    wgemm2<<<gR, 256, GEMM_SMEM>>>(xrh, xrl, wh + O_WIN_R, wl + O_WIN_R, trr, NR, DIN);
    split_bf16<<<CDIV(NU*H/4, 256), 256>>>(tuw, huh, hul, NU*H/4);
    split_bf16<<<CDIV(NR*H/4, 256), 256>>>(trr, hrh, hrl, NR*H/4);

    const float* bur[2] = {b1_ur, b2_ur};
    const float* bru[2] = {b1_ru, b2_ru};
    const float* brr[2] = {b1_rr, b2_rr};
    for (int l = 0; l < 2; l++) {
        int o_ur = O_L[l * 3 + 0], o_ru = O_L[l * 3 + 1], o_rr = O_L[l * 3 + 2];
        wgemm2<<<gU, 256, GEMM_SMEM>>>(huh, hul, wh + o_ur, wl + o_ur, tuw, NU, H);
        wgemm2<<<gR, 256, GEMM_SMEM>>>(hrh, hrl, wh + o_rr, wl + o_rr, trr, NR, H);
        wgemm2<<<gR, 256, GEMM_SMEM>>>(hrh, hrl, wh + o_ru, wl + o_ru, tru, NR, H);

        init_rest_acc<<<CDIV(NR * H4, 256), 256>>>(trr, bur[l], brr[l], accR);
        scatter_add<<<CDIV((size_t)EREV * 64, 256), 256>>>(tuw, rev_src, rev_dst, nrev, accR, EREV);
        scatter_add<<<CDIV((size_t)ENEAR * 64, 256), 256>>>(trr, near_src, near_dst, nnear, accR, ENEAR);

        init_bias<<<CDIV(NU * H4, 256), 256>>>(accU, bru[l], NU * H4);
        scatter_add<<<CDIV((size_t)EREV * 64, 256), 256>>>(tru, rev_dst, rev_src, nrev, accU, EREV);

        relu_split<<<CDIV(NU * H4, 256), 256>>>(accU, huh, hul, NU * H4);
        relu_split<<<CDIV(NR * H4, 256), 256>>>(accR, hrh, hrl, NR * H4);
    }

    // ---- output projection straight into d_out
    float* out = (float*)d_out;
    wgemm2<<<gU, 256, GEMM_SMEM>>>(huh, hul, wh + O_L[6], wl + O_L[6], out, NU, H);
    wgemm2<<<gR, 256, GEMM_SMEM>>>(hrh, hrl, wh + O_L[7], wl + O_L[7], out + (size_t)NU * H, NR, H);
}

// round 6
// speedup vs baseline: 1.9065x; 1.2885x over previous
#include <cuda_runtime.h>
#include <cuda_bf16.h>
#include <mma.h>
#include <cstddef>
#include <cstdint>

using namespace nvcuda;

#define CDIV(a,b) (((a)+(b)-1)/(b))

constexpr int NU    = 50000;
constexpr int NR    = 20000;
constexpr int DIN   = 512;
constexpr int H     = 256;
constexpr int H4    = H / 4;
constexpr int EREV  = 500000;
constexpr int ENEAR = 250000;

// ---------------- scratch (static device globals; no allocations) ----------
__device__ float g_tuw[(size_t)NU * H];
__device__ float g_trr[(size_t)NR * H];
__device__ float g_tru[(size_t)NR * H];
__device__ int   g_deg[NU + 3 * NR];
__device__ float g_inv_du[NU];
__device__ float g_inv_dr[NR];
__device__ float g_inv_ds[NR];
__device__ float g_inv_dd[NR];
// CSR buckets (by destination of each aggregation)
__device__ int   g_offRD[NR + 1], g_offND[NR + 1], g_offRS[NU + 1];
__device__ int   g_curRD[NR],     g_curND[NR],     g_curRS[NU];
__device__ int   g_ndRD[EREV],   g_ndND[ENEAR],   g_ndRS[EREV];
__device__ float g_nmRD[EREV],   g_nmND[ENEAR],   g_nmRS[EREV];
// bf16 hi/lo operand storage
__device__ __nv_bfloat16 g_xuh[(size_t)NU * DIN], g_xul[(size_t)NU * DIN];
__device__ __nv_bfloat16 g_xrh[(size_t)NR * DIN], g_xrl[(size_t)NR * DIN];
__device__ __nv_bfloat16 g_huh[(size_t)NU * H],   g_hul[(size_t)NU * H];
__device__ __nv_bfloat16 g_hrh[(size_t)NR * H],   g_hrl[(size_t)NR * H];
constexpr int WTOT = 2 * DIN * H + 8 * H * H;
__device__ __nv_bfloat16 g_wh[WTOT], g_wl[WTOT];

// ---------------- helpers ----------------------------------------------------
__device__ __forceinline__ uint32_t smem_u32(const void* p) {
    uint32_t a;
    asm("{ .reg .u64 t; cvta.to.shared.u64 t, %1; cvt.u32.u64 %0, t; }" : "=r"(a) : "l"(p));
    return a;
}
__device__ __forceinline__ void cp16(uint32_t dst, const void* src, bool ok) {
    int sz = ok ? 16 : 0;
    asm volatile("cp.async.cg.shared.global [%0], [%1], 16, %2;"
                 :: "r"(dst), "l"(src), "r"(sz) : "memory");
}
#define CP_COMMIT() asm volatile("cp.async.commit_group;" ::: "memory")
#define CP_WAIT1()  asm volatile("cp.async.wait_group 1;" ::: "memory")
#define CP_WAIT0()  asm volatile("cp.async.wait_group 0;" ::: "memory")

__device__ __forceinline__ uint2 split_pack(float4 v) {
    __nv_bfloat16 h0 = __float2bfloat16_rn(v.x), h1 = __float2bfloat16_rn(v.y);
    __nv_bfloat16 h2 = __float2bfloat16_rn(v.z), h3 = __float2bfloat16_rn(v.w);
    __nv_bfloat162 a = __halves2bfloat162(h0, h1);
    __nv_bfloat162 b = __halves2bfloat162(h2, h3);
    uint2 r;
    r.x = *(uint32_t*)&a; r.y = *(uint32_t*)&b;
    return r;
}
__device__ __forceinline__ uint2 split_pack_lo(float4 v, uint2 hi) {
    __nv_bfloat162 a = *(__nv_bfloat162*)&hi.x;
    __nv_bfloat162 b = *(__nv_bfloat162*)&hi.y;
    float4 r = make_float4(v.x - __bfloat162float(__low2bfloat16(a)),
                           v.y - __bfloat162float(__high2bfloat16(a)),
                           v.z - __bfloat162float(__low2bfloat16(b)),
                           v.w - __bfloat162float(__high2bfloat16(b)));
    return split_pack(r);
}

// ---------------- split kernel ----------------------------------------------
__global__ void split_bf16(const float* __restrict__ in,
                           __nv_bfloat16* __restrict__ h,
                           __nv_bfloat16* __restrict__ l, int n4) {
    int i = blockIdx.x * 256 + threadIdx.x;
    if (i >= n4) return;
    float4 v = ((const float4*)in)[i];
    uint2 hi = split_pack(v);
    uint2 lo = split_pack_lo(v, hi);
    ((uint2*)h)[i] = hi;
    ((uint2*)l)[i] = lo;
}

// ---------------- double-buffered bf16-split wmma GEMM ----------------------
constexpr int BM = 128, BN = 128, BK = 32;
constexpr int LDA = BK + 8;
constexpr int LDB = BN + 8;
constexpr int E_AH = 0;
constexpr int E_AL = E_AH + BM * LDA;
constexpr int E_BH = E_AL + BM * LDA;
constexpr int E_BL = E_BH + BK * LDB;
constexpr int STAGE_E = E_BL + BK * LDB;
constexpr int GEMM_SMEM = 2 * STAGE_E * 2;

__global__ __launch_bounds__(256) void wgemm2(const __nv_bfloat16* __restrict__ Ahg,
                                              const __nv_bfloat16* __restrict__ Alg,
                                              const __nv_bfloat16* __restrict__ Bhg,
                                              const __nv_bfloat16* __restrict__ Blg,
                                              float* __restrict__ C, int M, int K) {
    extern __shared__ __nv_bfloat16 sm[];
    uint32_t sbase = smem_u32(sm);

    int tid  = threadIdx.x;
    int wid  = tid >> 5;
    int lane = tid & 31;
    int row0 = blockIdx.y * BM;
    int col0 = blockIdx.x * BN;
    int wm   = wid >> 1;
    int wn   = wid & 1;

    wmma::fragment<wmma::accumulator, 16, 16, 16, float> acc[2][4];
#pragma unroll
    for (int mi = 0; mi < 2; mi++)
#pragma unroll
        for (int ni = 0; ni < 4; ni++) wmma::fill_fragment(acc[mi][ni], 0.f);

    auto load_stage = [&](int st, int k0) {
        uint32_t base = sbase + st * (STAGE_E * 2);
#pragma unroll
        for (int q = 0; q < 2; q++) {
            int i   = tid + 256 * q;
            int row = i >> 2;
            int c8  = (i & 3) << 3;
            bool ok = (row0 + row) < M;
            size_t off = (size_t)(ok ? row0 + row : 0) * K + k0 + c8;
            uint32_t d = base + (row * LDA + c8) * 2;
            cp16(d, Ahg + off, ok);
            cp16(d + E_AL * 2, Alg + off, ok);
        }
#pragma unroll
        for (int q = 0; q < 2; q++) {
            int i  = tid + 256 * q;
            int kk = i >> 4;
            int c8 = (i & 15) << 3;
            size_t off = (size_t)(k0 + kk) * 256 + col0 + c8;
            uint32_t d = base + E_BH * 2 + (kk * LDB + c8) * 2;
            cp16(d, Bhg + off, true);
            cp16(d + (E_BL - E_BH) * 2, Blg + off, true);
        }
    };

    int NC = K / BK;
    load_stage(0, 0);
    CP_COMMIT();

    for (int c = 0; c < NC; c++) {
        if (c + 1 < NC) load_stage((c + 1) & 1, (c + 1) * BK);
        CP_COMMIT();
        CP_WAIT1();
        __syncthreads();

        const __nv_bfloat16* sAh = sm + (c & 1) * STAGE_E + E_AH;
        const __nv_bfloat16* sAl = sm + (c & 1) * STAGE_E + E_AL;
        const __nv_bfloat16* sBh = sm + (c & 1) * STAGE_E + E_BH;
        const __nv_bfloat16* sBl = sm + (c & 1) * STAGE_E + E_BL;

#pragma unroll
        for (int kk = 0; kk < BK; kk += 16) {
            wmma::fragment<wmma::matrix_a, 16, 16, 16, __nv_bfloat16, wmma::row_major> ah[2], al[2];
#pragma unroll
            for (int mi = 0; mi < 2; mi++) {
                wmma::load_matrix_sync(ah[mi], sAh + (wm * 32 + mi * 16) * LDA + kk, LDA);
                wmma::load_matrix_sync(al[mi], sAl + (wm * 32 + mi * 16) * LDA + kk, LDA);
            }
#pragma unroll
            for (int ni = 0; ni < 4; ni++) {
                wmma::fragment<wmma::matrix_b, 16, 16, 16, __nv_bfloat16, wmma::row_major> bh, bl;
                wmma::load_matrix_sync(bh, sBh + kk * LDB + wn * 64 + ni * 16, LDB);
                wmma::load_matrix_sync(bl, sBl + kk * LDB + wn * 64 + ni * 16, LDB);
#pragma unroll
                for (int mi = 0; mi < 2; mi++) {
                    wmma::mma_sync(acc[mi][ni], ah[mi], bh, acc[mi][ni]);
                    wmma::mma_sync(acc[mi][ni], al[mi], bh, acc[mi][ni]);
                    wmma::mma_sync(acc[mi][ni], ah[mi], bl, acc[mi][ni]);
                }
            }
        }
        __syncthreads();
    }

    if (row0 + BM <= M) {
#pragma unroll
        for (int mi = 0; mi < 2; mi++)
#pragma unroll
            for (int ni = 0; ni < 4; ni++) {
                float* cp = C + (size_t)(row0 + wm * 32 + mi * 16) * 256
                              + col0 + wn * 64 + ni * 16;
                wmma::store_matrix_sync(cp, acc[mi][ni], 256, wmma::mem_row_major);
            }
    } else {
        CP_WAIT0();
        __syncthreads();
        float* stage = (float*)sm + wid * 416;
#pragma unroll
        for (int mi = 0; mi < 2; mi++)
#pragma unroll
            for (int ni = 0; ni < 4; ni++) {
                wmma::store_matrix_sync(stage, acc[mi][ni], 24, wmma::mem_row_major);
                __syncwarp();
#pragma unroll
                for (int j = 0; j < 8; j++) {
                    int e   = lane * 8 + j;
                    int r   = e >> 4, cc = e & 15;
                    int row = row0 + wm * 32 + mi * 16 + r;
                    if (row < M)
                        C[(size_t)row * 256 + col0 + wn * 64 + ni * 16 + cc] =
                            stage[r * 24 + cc];
                }
                __syncwarp();
            }
    }
}

// ---------------- CSR build kernels -----------------------------------------
__global__ void count_deg(const int* __restrict__ idx, int* __restrict__ deg, int E) {
    int i = blockIdx.x * 256 + threadIdx.x;
    if (i < E) atomicAdd(&deg[idx[i]], 1);
}

__global__ void make_inv(const int* __restrict__ deg, float* __restrict__ inv, int n, int add) {
    int i = blockIdx.x * 256 + threadIdx.x;
    if (i < n) {
        int d = deg[i] + add;
        inv[i] = d > 0 ? rsqrtf((float)d) : 0.f;
    }
}

// three exclusive scans, one per block (n <= 50000)
__global__ __launch_bounds__(1024) void scan3(const int* c0, int* o0, int n0,
                                              const int* c1, int* o1, int n1,
                                              const int* c2, int* o2, int n2) {
    const int* cnt = blockIdx.x == 0 ? c0 : blockIdx.x == 1 ? c1 : c2;
    int* off = blockIdx.x == 0 ? o0 : blockIdx.x == 1 ? o1 : o2;
    int n    = blockIdx.x == 0 ? n0 : blockIdx.x == 1 ? n1 : n2;
    __shared__ int tmp[1024];
    __shared__ int carry;
    if (threadIdx.x == 0) carry = 0;
    __syncthreads();
    for (int base = 0; base < n; base += 1024) {
        int i = base + (int)threadIdx.x;
        int v = (i < n) ? cnt[i] : 0;
        tmp[threadIdx.x] = v;
        __syncthreads();
#pragma unroll
        for (int s = 1; s < 1024; s <<= 1) {
            int t = (threadIdx.x >= (unsigned)s) ? tmp[threadIdx.x - s] : 0;
            __syncthreads();
            tmp[threadIdx.x] += t;
            __syncthreads();
        }
        if (i < n) off[i] = carry + tmp[threadIdx.x] - v;
        __syncthreads();
        if (threadIdx.x == 0) carry += tmp[1023];
        __syncthreads();
    }
    if (threadIdx.x == 0) off[n] = carry;
}

__global__ void fill_bucket(const int* __restrict__ key, const int* __restrict__ other,
                            const float* __restrict__ inv_k, const float* __restrict__ inv_o,
                            int* __restrict__ cursor,
                            int* __restrict__ nodes, float* __restrict__ norms, int E) {
    int i = blockIdx.x * 256 + threadIdx.x;
    if (i >= E) return;
    int k = key[i], o = other[i];
    int pos = atomicAdd(&cursor[k], 1);
    nodes[pos] = o;
    norms[pos] = inv_k[k] * inv_o[o];
}

// ---------------- fused gather + bias + relu + split -------------------------
// one 64-thread block per rest row; accumulates rev(by dst) + near(by dst)
__global__ __launch_bounds__(64) void gather_rest(const float* __restrict__ tuw,
                                                  const float* __restrict__ trr,
                                                  const float* __restrict__ bur,
                                                  const float* __restrict__ brr,
                                                  __nv_bfloat16* __restrict__ hh,
                                                  __nv_bfloat16* __restrict__ hl) {
    int row = blockIdx.x;
    int c   = threadIdx.x;          // float4 chunk 0..63
    float coef = g_inv_ds[row] * g_inv_dd[row];
    float4 a = ((const float4*)bur)[c];
    float4 b = ((const float4*)brr)[c];
    float4 t = ((const float4*)trr)[(size_t)row * 64 + c];
    float4 acc = make_float4(a.x + b.x + t.x * coef, a.y + b.y + t.y * coef,
                             a.z + b.z + t.z * coef, a.w + b.w + t.w * coef);

    int e  = g_offRD[row], e1 = g_offRD[row + 1];
    for (; e + 1 < e1; e += 2) {
        int s0 = g_ndRD[e], s1 = g_ndRD[e + 1];
        float n0 = g_nmRD[e], n1 = g_nmRD[e + 1];
        float4 v0 = ((const float4*)tuw)[(size_t)s0 * 64 + c];
        float4 v1 = ((const float4*)tuw)[(size_t)s1 * 64 + c];
        acc.x += v0.x * n0 + v1.x * n1; acc.y += v0.y * n0 + v1.y * n1;
        acc.z += v0.z * n0 + v1.z * n1; acc.w += v0.w * n0 + v1.w * n1;
    }
    if (e < e1) {
        int s0 = g_ndRD[e]; float n0 = g_nmRD[e];
        float4 v0 = ((const float4*)tuw)[(size_t)s0 * 64 + c];
        acc.x += v0.x * n0; acc.y += v0.y * n0; acc.z += v0.z * n0; acc.w += v0.w * n0;
    }

    e = g_offND[row]; e1 = g_offND[row + 1];
    for (; e + 1 < e1; e += 2) {
        int s0 = g_ndND[e], s1 = g_ndND[e + 1];
        float n0 = g_nmND[e], n1 = g_nmND[e + 1];
        float4 v0 = ((const float4*)trr)[(size_t)s0 * 64 + c];
        float4 v1 = ((const float4*)trr)[(size_t)s1 * 64 + c];
        acc.x += v0.x * n0 + v1.x * n1; acc.y += v0.y * n0 + v1.y * n1;
        acc.z += v0.z * n0 + v1.z * n1; acc.w += v0.w * n0 + v1.w * n1;
    }
    if (e < e1) {
        int s0 = g_ndND[e]; float n0 = g_nmND[e];
        float4 v0 = ((const float4*)trr)[(size_t)s0 * 64 + c];
        acc.x += v0.x * n0; acc.y += v0.y * n0; acc.z += v0.z * n0; acc.w += v0.w * n0;
    }

    acc = make_float4(fmaxf(acc.x, 0.f), fmaxf(acc.y, 0.f),
                      fmaxf(acc.z, 0.f), fmaxf(acc.w, 0.f));
    uint2 hi = split_pack(acc);
    uint2 lo = split_pack_lo(acc, hi);
    ((uint2*)hh)[(size_t)row * 64 + c] = hi;
    ((uint2*)hl)[(size_t)row * 64 + c] = lo;
}

// one 64-thread block per user row; accumulates rev edges grouped by src
__global__ __launch_bounds__(64) void gather_user(const float* __restrict__ tru,
                                                  const float* __restrict__ bru,
                                                  __nv_bfloat16* __restrict__ hh,
                                                  __nv_bfloat16* __restrict__ hl) {
    int row = blockIdx.x;
    int c   = threadIdx.x;
    float4 acc = ((const float4*)bru)[c];

    int e = g_offRS[row], e1 = g_offRS[row + 1];
    for (; e + 1 < e1; e += 2) {
        int s0 = g_ndRS[e], s1 = g_ndRS[e + 1];
        float n0 = g_nmRS[e], n1 = g_nmRS[e + 1];
        float4 v0 = ((const float4*)tru)[(size_t)s0 * 64 + c];
        float4 v1 = ((const float4*)tru)[(size_t)s1 * 64 + c];
        acc.x += v0.x * n0 + v1.x * n1; acc.y += v0.y * n0 + v1.y * n1;
        acc.z += v0.z * n0 + v1.z * n1; acc.w += v0.w * n0 + v1.w * n1;
    }
    if (e < e1) {
        int s0 = g_ndRS[e]; float n0 = g_nmRS[e];
        float4 v0 = ((const float4*)tru)[(size_t)s0 * 64 + c];
        acc.x += v0.x * n0; acc.y += v0.y * n0; acc.z += v0.z * n0; acc.w += v0.w * n0;
    }

    acc = make_float4(fmaxf(acc.x, 0.f), fmaxf(acc.y, 0.f),
                      fmaxf(acc.z, 0.f), fmaxf(acc.w, 0.f));
    uint2 hi = split_pack(acc);
    uint2 lo = split_pack_lo(acc, hi);
    ((uint2*)hh)[(size_t)row * 64 + c] = hi;
    ((uint2*)hl)[(size_t)row * 64 + c] = lo;
}

// ---------------- host orchestration ----------------------------------------
extern "C" void kernel_launch(void* const* d_in, const int* in_sizes, int n_in,
                              void* d_out, int out_size) {
    const float* x_user    = (const float*)d_in[0];
    const float* x_rest    = (const float*)d_in[1];
    const int*   rev_src   = (const int*)d_in[2];
    const int*   rev_dst   = (const int*)d_in[3];
    const int*   near_src  = (const int*)d_in[4];
    const int*   near_dst  = (const int*)d_in[5];
    const float* Win_user  = (const float*)d_in[6];
    const float* Win_rest  = (const float*)d_in[7];
    const float* W1_ur = (const float*)d_in[8];
    const float* b1_ur = (const float*)d_in[9];
    const float* W1_ru = (const float*)d_in[10];
    const float* b1_ru = (const float*)d_in[11];
    const float* W1_rr = (const float*)d_in[12];
    const float* b1_rr = (const float*)d_in[13];
    const float* W2_ur = (const float*)d_in[14];
    const float* b2_ur = (const float*)d_in[15];
    const float* W2_ru = (const float*)d_in[16];
    const float* b2_ru = (const float*)d_in[17];
    const float* W2_rr = (const float*)d_in[18];
    const float* b2_rr = (const float*)d_in[19];
    const float* Wout_user = (const float*)d_in[20];
    const float* Wout_rest = (const float*)d_in[21];

    cudaFuncSetAttribute(wgemm2, cudaFuncAttributeMaxDynamicSharedMemorySize, GEMM_SMEM);

    float *tuw, *trr, *tru;
    float *inv_du, *inv_dr, *inv_ds, *inv_dd;
    int *deg, *offRD, *offND, *offRS, *curRD, *curND, *curRS, *ndRD, *ndND, *ndRS;
    float *nmRD, *nmND, *nmRS;
    __nv_bfloat16 *xuh, *xul, *xrh, *xrl, *huh, *hul, *hrh, *hrl, *wh, *wl;
    cudaGetSymbolAddress((void**)&tuw, g_tuw);
    cudaGetSymbolAddress((void**)&trr, g_trr);
    cudaGetSymbolAddress((void**)&tru, g_tru);
    cudaGetSymbolAddress((void**)&inv_du, g_inv_du);
    cudaGetSymbolAddress((void**)&inv_dr, g_inv_dr);
    cudaGetSymbolAddress((void**)&inv_ds, g_inv_ds);
    cudaGetSymbolAddress((void**)&inv_dd, g_inv_dd);
    cudaGetSymbolAddress((void**)&deg, g_deg);
    cudaGetSymbolAddress((void**)&offRD, g_offRD);
    cudaGetSymbolAddress((void**)&offND, g_offND);
    cudaGetSymbolAddress((void**)&offRS, g_offRS);
    cudaGetSymbolAddress((void**)&curRD, g_curRD);
    cudaGetSymbolAddress((void**)&curND, g_curND);
    cudaGetSymbolAddress((void**)&curRS, g_curRS);
    cudaGetSymbolAddress((void**)&ndRD, g_ndRD);
    cudaGetSymbolAddress((void**)&ndND, g_ndND);
    cudaGetSymbolAddress((void**)&ndRS, g_ndRS);
    cudaGetSymbolAddress((void**)&nmRD, g_nmRD);
    cudaGetSymbolAddress((void**)&nmND, g_nmND);
    cudaGetSymbolAddress((void**)&nmRS, g_nmRS);
    cudaGetSymbolAddress((void**)&xuh, g_xuh);
    cudaGetSymbolAddress((void**)&xul, g_xul);
    cudaGetSymbolAddress((void**)&xrh, g_xrh);
    cudaGetSymbolAddress((void**)&xrl, g_xrl);
    cudaGetSymbolAddress((void**)&huh, g_huh);
    cudaGetSymbolAddress((void**)&hul, g_hul);
    cudaGetSymbolAddress((void**)&hrh, g_hrh);
    cudaGetSymbolAddress((void**)&hrl, g_hrl);
    cudaGetSymbolAddress((void**)&wh, g_wh);
    cudaGetSymbolAddress((void**)&wl, g_wl);

    int* du = deg;            // count rev_src  (user)
    int* dr = deg + NU;       // count rev_dst  (rest)
    int* ds = dr + NR;        // count near_src (rest)
    int* dd = ds + NR;        // count near_dst (rest)

    // ---- degrees
    cudaMemsetAsync(deg, 0, sizeof(int) * (NU + 3 * NR));
    count_deg<<<CDIV(EREV, 256), 256>>>(rev_src, du, EREV);
    count_deg<<<CDIV(EREV, 256), 256>>>(rev_dst, dr, EREV);
    count_deg<<<CDIV(ENEAR, 256), 256>>>(near_src, ds, ENEAR);
    count_deg<<<CDIV(ENEAR, 256), 256>>>(near_dst, dd, ENEAR);
    make_inv<<<CDIV(NU, 256), 256>>>(du, inv_du, NU, 0);
    make_inv<<<CDIV(NR, 256), 256>>>(dr, inv_dr, NR, 0);
    make_inv<<<CDIV(NR, 256), 256>>>(ds, inv_ds, NR, 1);
    make_inv<<<CDIV(NR, 256), 256>>>(dd, inv_dd, NR, 1);

    // ---- CSR build: scans, cursors, bucket fill (norm computed at fill)
    scan3<<<3, 1024>>>(dr, offRD, NR, dd, offND, NR, du, offRS, NU);
    cudaMemcpyAsync(curRD, offRD, sizeof(int) * NR, cudaMemcpyDeviceToDevice);
    cudaMemcpyAsync(curND, offND, sizeof(int) * NR, cudaMemcpyDeviceToDevice);
    cudaMemcpyAsync(curRS, offRS, sizeof(int) * NU, cudaMemcpyDeviceToDevice);
    fill_bucket<<<CDIV(EREV, 256), 256>>>(rev_dst, rev_src, inv_dr, inv_du, curRD, ndRD, nmRD, EREV);
    fill_bucket<<<CDIV(ENEAR, 256), 256>>>(near_dst, near_src, inv_dd, inv_ds, curND, ndND, nmND, ENEAR);
    fill_bucket<<<CDIV(EREV, 256), 256>>>(rev_src, rev_dst, inv_du, inv_dr, curRS, ndRS, nmRS, EREV);

    // ---- operand splits (weights + inputs)
    const int O_WIN_U = 0;
    const int O_WIN_R = DIN * H;
    const int O_L[8]  = {2*DIN*H,           2*DIN*H +   H*H, 2*DIN*H + 2*H*H,
                         2*DIN*H + 3*H*H,   2*DIN*H + 4*H*H, 2*DIN*H + 5*H*H,
                         2*DIN*H + 6*H*H,   2*DIN*H + 7*H*H};
    const float* wsrc[8] = {W1_ur, W1_ru, W1_rr, W2_ur, W2_ru, W2_rr, Wout_user, Wout_rest};
    split_bf16<<<CDIV(DIN*H/4, 256), 256>>>(Win_user, wh + O_WIN_U, wl + O_WIN_U, DIN*H/4);
    split_bf16<<<CDIV(DIN*H/4, 256), 256>>>(Win_rest, wh + O_WIN_R, wl + O_WIN_R, DIN*H/4);
    for (int i = 0; i < 8; i++)
        split_bf16<<<CDIV(H*H/4, 256), 256>>>(wsrc[i], wh + O_L[i], wl + O_L[i], H*H/4);
    split_bf16<<<CDIV(NU*DIN/4, 256), 256>>>(x_user, xuh, xul, NU*DIN/4);
    split_bf16<<<CDIV(NR*DIN/4, 256), 256>>>(x_rest, xrh, xrl, NR*DIN/4);

    dim3 gU(2, CDIV(NU, BM));
    dim3 gR(2, CDIV(NR, BM));

    // ---- input projection (K=512) -> fp32 temp -> split
    wgemm2<<<gU, 256, GEMM_SMEM>>>(xuh, xul, wh + O_WIN_U, wl + O_WIN_U, tuw, NU, DIN);
    wgemm2<<<gR, 256, GEMM_SMEM>>>(xrh, xrl, wh + O_WIN_R, wl + O_WIN_R, trr, NR, DIN);
    split_bf16<<<CDIV(NU*H/4, 256), 256>>>(tuw, huh, hul, NU*H/4);
    split_bf16<<<CDIV(NR*H/4, 256), 256>>>(trr, hrh, hrl, NR*H/4);

    const float* bur[2] = {b1_ur, b2_ur};
    const float* bru[2] = {b1_ru, b2_ru};
    const float* brr[2] = {b1_rr, b2_rr};
    for (int l = 0; l < 2; l++) {
        int o_ur = O_L[l * 3 + 0], o_ru = O_L[l * 3 + 1], o_rr = O_L[l * 3 + 2];
        wgemm2<<<gU, 256, GEMM_SMEM>>>(huh, hul, wh + o_ur, wl + o_ur, tuw, NU, H);
        wgemm2<<<gR, 256, GEMM_SMEM>>>(hrh, hrl, wh + o_rr, wl + o_rr, trr, NR, H);
        wgemm2<<<gR, 256, GEMM_SMEM>>>(hrh, hrl, wh + o_ru, wl + o_ru, tru, NR, H);

        gather_rest<<<NR, 64>>>(tuw, trr, bur[l], brr[l], hrh, hrl);
        gather_user<<<NU, 64>>>(tru, bru[l], huh, hul);
    }

    // ---- output projection straight into d_out
    float* out = (float*)d_out;
    wgemm2<<<gU, 256, GEMM_SMEM>>>(huh, hul, wh + O_L[6], wl + O_L[6], out, NU, H);
    wgemm2<<<gR, 256, GEMM_SMEM>>>(hrh, hrl, wh + O_L[7], wl + O_L[7], out + (size_t)NU * H, NR, H);
}

// round 8
// speedup vs baseline: 2.4234x; 1.2712x over previous
#include <cuda_runtime.h>
#include <cuda_bf16.h>
#include <mma.h>
#include <cstddef>
#include <cstdint>

using namespace nvcuda;

#define CDIV(a,b) (((a)+(b)-1)/(b))

constexpr int NU    = 50000;
constexpr int NR    = 20000;
constexpr int DIN   = 512;
constexpr int H     = 256;
constexpr int EREV  = 500000;
constexpr int ENEAR = 250000;

// ---------------- scratch (static device globals; no allocations) ----------
__device__ float g_tuw[(size_t)NU * H];
__device__ float g_trr[(size_t)NR * H];
__device__ float g_tru[(size_t)NR * H];
__device__ int   g_deg[NU + 3 * NR];
__device__ float g_inv_du[NU];
__device__ float g_inv_dr[NR];
__device__ float g_inv_ds[NR];
__device__ float g_inv_dd[NR];
// CSR buckets (by destination of each aggregation)
__device__ int   g_offRD[NR + 1], g_offND[NR + 1], g_offRS[NU + 1];
__device__ int   g_curRD[NR],     g_curND[NR],     g_curRS[NU];
__device__ int   g_ndRD[EREV],   g_ndND[ENEAR],   g_ndRS[EREV];
__device__ float g_nmRD[EREV],   g_nmND[ENEAR],   g_nmRS[EREV];
// bf16 hi/lo operand storage (activations ping-pong A/B)
__device__ __nv_bfloat16 g_xuh[(size_t)NU * DIN], g_xul[(size_t)NU * DIN];
__device__ __nv_bfloat16 g_xrh[(size_t)NR * DIN], g_xrl[(size_t)NR * DIN];
__device__ __nv_bfloat16 g_huAh[(size_t)NU * H], g_huAl[(size_t)NU * H];
__device__ __nv_bfloat16 g_huBh[(size_t)NU * H], g_huBl[(size_t)NU * H];
__device__ __nv_bfloat16 g_hrAh[(size_t)NR * H], g_hrAl[(size_t)NR * H];
__device__ __nv_bfloat16 g_hrBh[(size_t)NR * H], g_hrBl[(size_t)NR * H];
constexpr int WTOT = 2 * DIN * H + 8 * H * H;
__device__ __nv_bfloat16 g_wh[WTOT], g_wl[WTOT];

// ---------------- helpers ----------------------------------------------------
__device__ __forceinline__ uint32_t smem_u32(const void* p) {
    uint32_t a;
    asm("{ .reg .u64 t; cvta.to.shared.u64 t, %1; cvt.u32.u64 %0, t; }" : "=r"(a) : "l"(p));
    return a;
}
__device__ __forceinline__ void cp16(uint32_t dst, const void* src, bool ok) {
    int sz = ok ? 16 : 0;
    asm volatile("cp.async.cg.shared.global [%0], [%1], 16, %2;"
                 :: "r"(dst), "l"(src), "r"(sz) : "memory");
}
#define CP_COMMIT() asm volatile("cp.async.commit_group;" ::: "memory")
#define CP_WAIT1()  asm volatile("cp.async.wait_group 1;" ::: "memory")

__device__ __forceinline__ uint2 split_pack(float4 v) {
    __nv_bfloat16 h0 = __float2bfloat16_rn(v.x), h1 = __float2bfloat16_rn(v.y);
    __nv_bfloat16 h2 = __float2bfloat16_rn(v.z), h3 = __float2bfloat16_rn(v.w);
    __nv_bfloat162 a = __halves2bfloat162(h0, h1);
    __nv_bfloat162 b = __halves2bfloat162(h2, h3);
    uint2 r;
    r.x = *(uint32_t*)&a; r.y = *(uint32_t*)&b;
    return r;
}
__device__ __forceinline__ uint2 split_pack_lo(float4 v, uint2 hi) {
    __nv_bfloat162 a = *(__nv_bfloat162*)&hi.x;
    __nv_bfloat162 b = *(__nv_bfloat162*)&hi.y;
    float4 r = make_float4(v.x - __bfloat162float(__low2bfloat16(a)),
                           v.y - __bfloat162float(__high2bfloat16(a)),
                           v.z - __bfloat162float(__low2bfloat16(b)),
                           v.w - __bfloat162float(__high2bfloat16(b)));
    return split_pack(r);
}

// ---------------- split kernel (weights + raw inputs) ------------------------
__global__ void split_bf16(const float* __restrict__ in,
                           __nv_bfloat16* __restrict__ h,
                           __nv_bfloat16* __restrict__ l, int n4) {
    int i = blockIdx.x * 256 + threadIdx.x;
    if (i >= n4) return;
    float4 v = ((const float4*)in)[i];
    uint2 hi = split_pack(v);
    uint2 lo = split_pack_lo(v, hi);
    ((uint2*)h)[i] = hi;
    ((uint2*)l)[i] = lo;
}

// ---------------- double-buffered bf16-split wmma GEMM ----------------------
// fp32 output (C) when Ch==nullptr, else fused hi/lo bf16 split output.
constexpr int BM = 128, BN = 128, BK = 32;
constexpr int LDA = BK + 8;
constexpr int LDB = BN + 8;
constexpr int E_AH = 0;
constexpr int E_AL = E_AH + BM * LDA;
constexpr int E_BH = E_AL + BM * LDA;
constexpr int E_BL = E_BH + BK * LDB;
constexpr int STAGE_E = E_BL + BK * LDB;
constexpr int GEMM_SMEM = 2 * STAGE_E * 2;

__global__ __launch_bounds__(256) void wgemm2(const __nv_bfloat16* __restrict__ Ahg,
                                              const __nv_bfloat16* __restrict__ Alg,
                                              const __nv_bfloat16* __restrict__ Bhg,
                                              const __nv_bfloat16* __restrict__ Blg,
                                              float* __restrict__ C,
                                              __nv_bfloat16* __restrict__ Ch,
                                              __nv_bfloat16* __restrict__ Cl,
                                              int M, int K) {
    extern __shared__ __nv_bfloat16 sm[];
    uint32_t sbase = smem_u32(sm);

    int tid  = threadIdx.x;
    int wid  = tid >> 5;
    int lane = tid & 31;
    int row0 = blockIdx.y * BM;
    int col0 = blockIdx.x * BN;
    int wm   = wid >> 1;
    int wn   = wid & 1;

    wmma::fragment<wmma::accumulator, 16, 16, 16, float> acc[2][4];
#pragma unroll
    for (int mi = 0; mi < 2; mi++)
#pragma unroll
        for (int ni = 0; ni < 4; ni++) wmma::fill_fragment(acc[mi][ni], 0.f);

    auto load_stage = [&](int st, int k0) {
        uint32_t base = sbase + st * (STAGE_E * 2);
#pragma unroll
        for (int q = 0; q < 2; q++) {
            int i   = tid + 256 * q;
            int row = i >> 2;
            int c8  = (i & 3) << 3;
            bool ok = (row0 + row) < M;
            size_t off = (size_t)(ok ? row0 + row : 0) * K + k0 + c8;
            uint32_t d = base + (row * LDA + c8) * 2;
            cp16(d, Ahg + off, ok);
            cp16(d + E_AL * 2, Alg + off, ok);
        }
#pragma unroll
        for (int q = 0; q < 2; q++) {
            int i  = tid + 256 * q;
            int kk = i >> 4;
            int c8 = (i & 15) << 3;
            size_t off = (size_t)(k0 + kk) * 256 + col0 + c8;
            uint32_t d = base + E_BH * 2 + (kk * LDB + c8) * 2;
            cp16(d, Bhg + off, true);
            cp16(d + (E_BL - E_BH) * 2, Blg + off, true);
        }
    };

    int NC = K / BK;
    load_stage(0, 0);
    CP_COMMIT();

    for (int c = 0; c < NC; c++) {
        if (c + 1 < NC) load_stage((c + 1) & 1, (c + 1) * BK);
        CP_COMMIT();
        CP_WAIT1();
        __syncthreads();

        const __nv_bfloat16* sAh = sm + (c & 1) * STAGE_E + E_AH;
        const __nv_bfloat16* sAl = sm + (c & 1) * STAGE_E + E_AL;
        const __nv_bfloat16* sBh = sm + (c & 1) * STAGE_E + E_BH;
        const __nv_bfloat16* sBl = sm + (c & 1) * STAGE_E + E_BL;

#pragma unroll
        for (int kk = 0; kk < BK; kk += 16) {
            wmma::fragment<wmma::matrix_a, 16, 16, 16, __nv_bfloat16, wmma::row_major> ah[2], al[2];
#pragma unroll
            for (int mi = 0; mi < 2; mi++) {
                wmma::load_matrix_sync(ah[mi], sAh + (wm * 32 + mi * 16) * LDA + kk, LDA);
                wmma::load_matrix_sync(al[mi], sAl + (wm * 32 + mi * 16) * LDA + kk, LDA);
            }
#pragma unroll
            for (int ni = 0; ni < 4; ni++) {
                wmma::fragment<wmma::matrix_b, 16, 16, 16, __nv_bfloat16, wmma::row_major> bh, bl;
                wmma::load_matrix_sync(bh, sBh + kk * LDB + wn * 64 + ni * 16, LDB);
                wmma::load_matrix_sync(bl, sBl + kk * LDB + wn * 64 + ni * 16, LDB);
#pragma unroll
                for (int mi = 0; mi < 2; mi++) {
                    wmma::mma_sync(acc[mi][ni], ah[mi], bh, acc[mi][ni]);
                    wmma::mma_sync(acc[mi][ni], al[mi], bh, acc[mi][ni]);
                    wmma::mma_sync(acc[mi][ni], ah[mi], bl, acc[mi][ni]);
                }
            }
        }
        __syncthreads();
    }

    if (Ch != nullptr) {
        // fused split epilogue (bf16 hi/lo); per-warp smem staging, row-guarded
        float* stage = (float*)sm + wid * 512;
#pragma unroll
        for (int mi = 0; mi < 2; mi++)
#pragma unroll
            for (int ni = 0; ni < 4; ni++) {
                wmma::store_matrix_sync(stage, acc[mi][ni], 20, wmma::mem_row_major);
                __syncwarp();
#pragma unroll
                for (int jj = 0; jj < 4; jj++) {
                    int e2 = lane * 4 + jj;      // pair index
                    int r  = e2 >> 3;
                    int c0 = (e2 & 7) * 2;
                    int row = row0 + wm * 32 + mi * 16 + r;
                    if (row < M) {
                        float v0 = stage[r * 20 + c0], v1 = stage[r * 20 + c0 + 1];
                        __nv_bfloat16 h0 = __float2bfloat16_rn(v0);
                        __nv_bfloat16 h1 = __float2bfloat16_rn(v1);
                        __nv_bfloat16 l0 = __float2bfloat16_rn(v0 - __bfloat162float(h0));
                        __nv_bfloat16 l1 = __float2bfloat16_rn(v1 - __bfloat162float(h1));
                        size_t off = (size_t)row * 256 + col0 + wn * 64 + ni * 16 + c0;
                        *(__nv_bfloat162*)(Ch + off) = __halves2bfloat162(h0, h1);
                        *(__nv_bfloat162*)(Cl + off) = __halves2bfloat162(l0, l1);
                    }
                }
                __syncwarp();
            }
    } else if (row0 + BM <= M) {
#pragma unroll
        for (int mi = 0; mi < 2; mi++)
#pragma unroll
            for (int ni = 0; ni < 4; ni++) {
                float* cp = C + (size_t)(row0 + wm * 32 + mi * 16) * 256
                              + col0 + wn * 64 + ni * 16;
                wmma::store_matrix_sync(cp, acc[mi][ni], 256, wmma::mem_row_major);
            }
    } else {
        float* stage = (float*)sm + wid * 512;
#pragma unroll
        for (int mi = 0; mi < 2; mi++)
#pragma unroll
            for (int ni = 0; ni < 4; ni++) {
                wmma::store_matrix_sync(stage, acc[mi][ni], 20, wmma::mem_row_major);
                __syncwarp();
#pragma unroll
                for (int j = 0; j < 8; j++) {
                    int e   = lane * 8 + j;
                    int r   = e >> 4, cc = e & 15;
                    int row = row0 + wm * 32 + mi * 16 + r;
                    if (row < M)
                        C[(size_t)row * 256 + col0 + wn * 64 + ni * 16 + cc] =
                            stage[r * 20 + cc];
                }
                __syncwarp();
            }
    }
}

// ---------------- CSR build kernels -----------------------------------------
__global__ void count_deg(const int* __restrict__ idx, int* __restrict__ deg, int E) {
    int i = blockIdx.x * 256 + threadIdx.x;
    if (i < E) atomicAdd(&deg[idx[i]], 1);
}

__global__ void make_inv(const int* __restrict__ deg, float* __restrict__ inv, int n, int add) {
    int i = blockIdx.x * 256 + threadIdx.x;
    if (i < n) {
        int d = deg[i] + add;
        inv[i] = d > 0 ? rsqrtf((float)d) : 0.f;
    }
}

__global__ __launch_bounds__(1024) void scan3(const int* c0, int* o0, int n0,
                                              const int* c1, int* o1, int n1,
                                              const int* c2, int* o2, int n2) {
    const int* cnt = blockIdx.x == 0 ? c0 : blockIdx.x == 1 ? c1 : c2;
    int* off = blockIdx.x == 0 ? o0 : blockIdx.x == 1 ? o1 : o2;
    int n    = blockIdx.x == 0 ? n0 : blockIdx.x == 1 ? n1 : n2;
    __shared__ int tmp[1024];
    __shared__ int carry;
    if (threadIdx.x == 0) carry = 0;
    __syncthreads();
    for (int base = 0; base < n; base += 1024) {
        int i = base + (int)threadIdx.x;
        int v = (i < n) ? cnt[i] : 0;
        tmp[threadIdx.x] = v;
        __syncthreads();
#pragma unroll
        for (int s = 1; s < 1024; s <<= 1) {
            int t = (threadIdx.x >= (unsigned)s) ? tmp[threadIdx.x - s] : 0;
            __syncthreads();
            tmp[threadIdx.x] += t;
            __syncthreads();
        }
        if (i < n) off[i] = carry + tmp[threadIdx.x] - v;
        __syncthreads();
        if (threadIdx.x == 0) carry += tmp[1023];
        __syncthreads();
    }
    if (threadIdx.x == 0) off[n] = carry;
}

__global__ void fill_bucket(const int* __restrict__ key, const int* __restrict__ other,
                            const float* __restrict__ inv_k, const float* __restrict__ inv_o,
                            int* __restrict__ cursor,
                            int* __restrict__ nodes, float* __restrict__ norms, int E) {
    int i = blockIdx.x * 256 + threadIdx.x;
    if (i >= E) return;
    int k = key[i], o = other[i];
    int pos = atomicAdd(&cursor[k], 1);
    nodes[pos] = o;
    norms[pos] = inv_k[k] * inv_o[o];
}

// ---------------- fused gather + bias + relu + split -------------------------
__global__ __launch_bounds__(64) void gather_rest(const float* __restrict__ tuw,
                                                  const float* __restrict__ trr,
                                                  const float* __restrict__ bur,
                                                  const float* __restrict__ brr,
                                                  __nv_bfloat16* __restrict__ hh,
                                                  __nv_bfloat16* __restrict__ hl) {
    int row = blockIdx.x;
    int c   = threadIdx.x;
    float coef = g_inv_ds[row] * g_inv_dd[row];
    float4 a = ((const float4*)bur)[c];
    float4 b = ((const float4*)brr)[c];
    float4 t = ((const float4*)trr)[(size_t)row * 64 + c];
    float4 acc = make_float4(a.x + b.x + t.x * coef, a.y + b.y + t.y * coef,
                             a.z + b.z + t.z * coef, a.w + b.w + t.w * coef);

    int e  = g_offRD[row], e1 = g_offRD[row + 1];
    for (; e + 1 < e1; e += 2) {
        int s0 = g_ndRD[e], s1 = g_ndRD[e + 1];
        float n0 = g_nmRD[e], n1 = g_nmRD[e + 1];
        float4 v0 = ((const float4*)tuw)[(size_t)s0 * 64 + c];
        float4 v1 = ((const float4*)tuw)[(size_t)s1 * 64 + c];
        acc.x += v0.x * n0 + v1.x * n1; acc.y += v0.y * n0 + v1.y * n1;
        acc.z += v0.z * n0 + v1.z * n1; acc.w += v0.w * n0 + v1.w * n1;
    }
    if (e < e1) {
        int s0 = g_ndRD[e]; float n0 = g_nmRD[e];
        float4 v0 = ((const float4*)tuw)[(size_t)s0 * 64 + c];
        acc.x += v0.x * n0; acc.y += v0.y * n0; acc.z += v0.z * n0; acc.w += v0.w * n0;
    }

    e = g_offND[row]; e1 = g_offND[row + 1];
    for (; e + 1 < e1; e += 2) {
        int s0 = g_ndND[e], s1 = g_ndND[e + 1];
        float n0 = g_nmND[e], n1 = g_nmND[e + 1];
        float4 v0 = ((const float4*)trr)[(size_t)s0 * 64 + c];
        float4 v1 = ((const float4*)trr)[(size_t)s1 * 64 + c];
        acc.x += v0.x * n0 + v1.x * n1; acc.y += v0.y * n0 + v1.y * n1;
        acc.z += v0.z * n0 + v1.z * n1; acc.w += v0.w * n0 + v1.w * n1;
    }
    if (e < e1) {
        int s0 = g_ndND[e]; float n0 = g_nmND[e];
        float4 v0 = ((const float4*)trr)[(size_t)s0 * 64 + c];
        acc.x += v0.x * n0; acc.y += v0.y * n0; acc.z += v0.z * n0; acc.w += v0.w * n0;
    }

    acc = make_float4(fmaxf(acc.x, 0.f), fmaxf(acc.y, 0.f),
                      fmaxf(acc.z, 0.f), fmaxf(acc.w, 0.f));
    uint2 hi = split_pack(acc);
    uint2 lo = split_pack_lo(acc, hi);
    ((uint2*)hh)[(size_t)row * 64 + c] = hi;
    ((uint2*)hl)[(size_t)row * 64 + c] = lo;
}

__global__ __launch_bounds__(64) void gather_user(const float* __restrict__ tru,
                                                  const float* __restrict__ bru,
                                                  __nv_bfloat16* __restrict__ hh,
                                                  __nv_bfloat16* __restrict__ hl) {
    int row = blockIdx.x;
    int c   = threadIdx.x;
    float4 acc = ((const float4*)bru)[c];

    int e = g_offRS[row], e1 = g_offRS[row + 1];
    for (; e + 1 < e1; e += 2) {
        int s0 = g_ndRS[e], s1 = g_ndRS[e + 1];
        float n0 = g_nmRS[e], n1 = g_nmRS[e + 1];
        float4 v0 = ((const float4*)tru)[(size_t)s0 * 64 + c];
        float4 v1 = ((const float4*)tru)[(size_t)s1 * 64 + c];
        acc.x += v0.x * n0 + v1.x * n1; acc.y += v0.y * n0 + v1.y * n1;
        acc.z += v0.z * n0 + v1.z * n1; acc.w += v0.w * n0 + v1.w * n1;
    }
    if (e < e1) {
        int s0 = g_ndRS[e]; float n0 = g_nmRS[e];
        float4 v0 = ((const float4*)tru)[(size_t)s0 * 64 + c];
        acc.x += v0.x * n0; acc.y += v0.y * n0; acc.z += v0.z * n0; acc.w += v0.w * n0;
    }

    acc = make_float4(fmaxf(acc.x, 0.f), fmaxf(acc.y, 0.f),
                      fmaxf(acc.z, 0.f), fmaxf(acc.w, 0.f));
    uint2 hi = split_pack(acc);
    uint2 lo = split_pack_lo(acc, hi);
    ((uint2*)hh)[(size_t)row * 64 + c] = hi;
    ((uint2*)hl)[(size_t)row * 64 + c] = lo;
}

// ---------------- host orchestration ----------------------------------------
extern "C" void kernel_launch(void* const* d_in, const int* in_sizes, int n_in,
                              void* d_out, int out_size) {
    const float* x_user    = (const float*)d_in[0];
    const float* x_rest    = (const float*)d_in[1];
    const int*   rev_src   = (const int*)d_in[2];
    const int*   rev_dst   = (const int*)d_in[3];
    const int*   near_src  = (const int*)d_in[4];
    const int*   near_dst  = (const int*)d_in[5];
    const float* Win_user  = (const float*)d_in[6];
    const float* Win_rest  = (const float*)d_in[7];
    const float* W1_ur = (const float*)d_in[8];
    const float* b1_ur = (const float*)d_in[9];
    const float* W1_ru = (const float*)d_in[10];
    const float* b1_ru = (const float*)d_in[11];
    const float* W1_rr = (const float*)d_in[12];
    const float* b1_rr = (const float*)d_in[13];
    const float* W2_ur = (const float*)d_in[14];
    const float* b2_ur = (const float*)d_in[15];
    const float* W2_ru = (const float*)d_in[16];
    const float* b2_ru = (const float*)d_in[17];
    const float* W2_rr = (const float*)d_in[18];
    const float* b2_rr = (const float*)d_in[19];
    const float* Wout_user = (const float*)d_in[20];
    const float* Wout_rest = (const float*)d_in[21];

    cudaFuncSetAttribute(wgemm2, cudaFuncAttributeMaxDynamicSharedMemorySize, GEMM_SMEM);

    // side stream + events (host objects; created once, reused; never destroyed
    // mid-capture). No device memory involved.
    static cudaStream_t s2 = nullptr;
    static cudaEvent_t evFork, evCSR, evT1, evT2, evGU1, evGU2, evJoin;
    if (!s2) {
        cudaStreamCreateWithFlags(&s2, cudaStreamNonBlocking);
        cudaEventCreateWithFlags(&evFork, cudaEventDisableTiming);
        cudaEventCreateWithFlags(&evCSR,  cudaEventDisableTiming);
        cudaEventCreateWithFlags(&evT1,   cudaEventDisableTiming);
        cudaEventCreateWithFlags(&evT2,   cudaEventDisableTiming);
        cudaEventCreateWithFlags(&evGU1,  cudaEventDisableTiming);
        cudaEventCreateWithFlags(&evGU2,  cudaEventDisableTiming);
        cudaEventCreateWithFlags(&evJoin, cudaEventDisableTiming);
    }

    float *tuw, *trr, *tru;
    float *inv_du, *inv_dr, *inv_ds, *inv_dd;
    int *deg, *offRD, *offND, *offRS, *curRD, *curND, *curRS, *ndRD, *ndND, *ndRS;
    float *nmRD, *nmND, *nmRS;
    __nv_bfloat16 *xuh, *xul, *xrh, *xrl, *wh, *wl;
    __nv_bfloat16 *huAh, *huAl, *huBh, *huBl, *hrAh, *hrAl, *hrBh, *hrBl;
    cudaGetSymbolAddress((void**)&tuw, g_tuw);
    cudaGetSymbolAddress((void**)&trr, g_trr);
    cudaGetSymbolAddress((void**)&tru, g_tru);
    cudaGetSymbolAddress((void**)&inv_du, g_inv_du);
    cudaGetSymbolAddress((void**)&inv_dr, g_inv_dr);
    cudaGetSymbolAddress((void**)&inv_ds, g_inv_ds);
    cudaGetSymbolAddress((void**)&inv_dd, g_inv_dd);
    cudaGetSymbolAddress((void**)&deg, g_deg);
    cudaGetSymbolAddress((void**)&offRD, g_offRD);
    cudaGetSymbolAddress((void**)&offND, g_offND);
    cudaGetSymbolAddress((void**)&offRS, g_offRS);
    cudaGetSymbolAddress((void**)&curRD, g_curRD);
    cudaGetSymbolAddress((void**)&curND, g_curND);
    cudaGetSymbolAddress((void**)&curRS, g_curRS);
    cudaGetSymbolAddress((void**)&ndRD, g_ndRD);
    cudaGetSymbolAddress((void**)&ndND, g_ndND);
    cudaGetSymbolAddress((void**)&ndRS, g_ndRS);
    cudaGetSymbolAddress((void**)&nmRD, g_nmRD);
    cudaGetSymbolAddress((void**)&nmND, g_nmND);
    cudaGetSymbolAddress((void**)&nmRS, g_nmRS);
    cudaGetSymbolAddress((void**)&xuh, g_xuh);
    cudaGetSymbolAddress((void**)&xul, g_xul);
    cudaGetSymbolAddress((void**)&xrh, g_xrh);
    cudaGetSymbolAddress((void**)&xrl, g_xrl);
    cudaGetSymbolAddress((void**)&huAh, g_huAh);
    cudaGetSymbolAddress((void**)&huAl, g_huAl);
    cudaGetSymbolAddress((void**)&huBh, g_huBh);
    cudaGetSymbolAddress((void**)&huBl, g_huBl);
    cudaGetSymbolAddress((void**)&hrAh, g_hrAh);
    cudaGetSymbolAddress((void**)&hrAl, g_hrAl);
    cudaGetSymbolAddress((void**)&hrBh, g_hrBh);
    cudaGetSymbolAddress((void**)&hrBl, g_hrBl);
    cudaGetSymbolAddress((void**)&wh, g_wh);
    cudaGetSymbolAddress((void**)&wl, g_wl);

    int* du = deg;
    int* dr = deg + NU;
    int* ds = dr + NR;
    int* dd = ds + NR;

    const int O_WIN_U = 0;
    const int O_WIN_R = DIN * H;
    const int O_L[8]  = {2*DIN*H,           2*DIN*H +   H*H, 2*DIN*H + 2*H*H,
                         2*DIN*H + 3*H*H,   2*DIN*H + 4*H*H, 2*DIN*H + 5*H*H,
                         2*DIN*H + 6*H*H,   2*DIN*H + 7*H*H};
    const float* wsrc[8] = {W1_ur, W1_ru, W1_rr, W2_ur, W2_ru, W2_rr, Wout_user, Wout_rest};

    dim3 gU(2, CDIV(NU, BM));
    dim3 gR(2, CDIV(NR, BM));

    // ===== fork s2 off the capture stream =====
    cudaEventRecord(evFork, 0);
    cudaStreamWaitEvent(s2, evFork, 0);

    // ----- stream0: CSR build -----
    cudaMemsetAsync(deg, 0, sizeof(int) * (NU + 3 * NR));
    count_deg<<<CDIV(EREV, 256), 256>>>(rev_src, du, EREV);
    count_deg<<<CDIV(EREV, 256), 256>>>(rev_dst, dr, EREV);
    count_deg<<<CDIV(ENEAR, 256), 256>>>(near_src, ds, ENEAR);
    count_deg<<<CDIV(ENEAR, 256), 256>>>(near_dst, dd, ENEAR);
    make_inv<<<CDIV(NU, 256), 256>>>(du, inv_du, NU, 0);
    make_inv<<<CDIV(NR, 256), 256>>>(dr, inv_dr, NR, 0);
    make_inv<<<CDIV(NR, 256), 256>>>(ds, inv_ds, NR, 1);
    make_inv<<<CDIV(NR, 256), 256>>>(dd, inv_dd, NR, 1);
    scan3<<<3, 1024>>>(dr, offRD, NR, dd, offND, NR, du, offRS, NU);
    cudaMemcpyAsync(curRD, offRD, sizeof(int) * NR, cudaMemcpyDeviceToDevice);
    cudaMemcpyAsync(curND, offND, sizeof(int) * NR, cudaMemcpyDeviceToDevice);
    cudaMemcpyAsync(curRS, offRS, sizeof(int) * NU, cudaMemcpyDeviceToDevice);
    fill_bucket<<<CDIV(EREV, 256), 256>>>(rev_dst, rev_src, inv_dr, inv_du, curRD, ndRD, nmRD, EREV);
    fill_bucket<<<CDIV(ENEAR, 256), 256>>>(near_dst, near_src, inv_dd, inv_ds, curND, ndND, nmND, ENEAR);
    fill_bucket<<<CDIV(EREV, 256), 256>>>(rev_src, rev_dst, inv_du, inv_dr, curRS, ndRS, nmRS, EREV);
    cudaEventRecord(evCSR, 0);

    // ----- s2: splits + input projection (split-fused epilogue) -----
    split_bf16<<<CDIV(DIN*H/4, 256), 256, 0, s2>>>(Win_user, wh + O_WIN_U, wl + O_WIN_U, DIN*H/4);
    split_bf16<<<CDIV(DIN*H/4, 256), 256, 0, s2>>>(Win_rest, wh + O_WIN_R, wl + O_WIN_R, DIN*H/4);
    for (int i = 0; i < 8; i++)
        split_bf16<<<CDIV(H*H/4, 256), 256, 0, s2>>>(wsrc[i], wh + O_L[i], wl + O_L[i], H*H/4);
    split_bf16<<<CDIV(NU*DIN/4, 256), 256, 0, s2>>>(x_user, xuh, xul, NU*DIN/4);
    split_bf16<<<CDIV(NR*DIN/4, 256), 256, 0, s2>>>(x_rest, xrh, xrl, NR*DIN/4);

    wgemm2<<<gU, 256, GEMM_SMEM, s2>>>(xuh, xul, wh + O_WIN_U, wl + O_WIN_U,
                                       nullptr, huAh, huAl, NU, DIN);
    wgemm2<<<gR, 256, GEMM_SMEM, s2>>>(xrh, xrl, wh + O_WIN_R, wl + O_WIN_R,
                                       nullptr, hrAh, hrAl, NR, DIN);

    const float* bur[2] = {b1_ur, b2_ur};
    const float* bru[2] = {b1_ru, b2_ru};
    const float* brr[2] = {b1_rr, b2_rr};

    // ===== layer 1 (reads A buffers, gathers write B buffers) =====
    wgemm2<<<gR, 256, GEMM_SMEM, s2>>>(hrAh, hrAl, wh + O_L[1], wl + O_L[1],
                                       tru, nullptr, nullptr, NR, H);
    cudaEventRecord(evT1, s2);
    // stream0: gather_user(L1) overlapped with s2's tuw/trr/gather_rest
    cudaStreamWaitEvent(0, evT1, 0);
    gather_user<<<NU, 64>>>(tru, bru[0], huBh, huBl);
    cudaEventRecord(evGU1, 0);
    // s2 continues
    wgemm2<<<gU, 256, GEMM_SMEM, s2>>>(huAh, huAl, wh + O_L[0], wl + O_L[0],
                                       tuw, nullptr, nullptr, NU, H);
    wgemm2<<<gR, 256, GEMM_SMEM, s2>>>(hrAh, hrAl, wh + O_L[2], wl + O_L[2],
                                       trr, nullptr, nullptr, NR, H);
    cudaStreamWaitEvent(s2, evCSR, 0);
    gather_rest<<<NR, 64, 0, s2>>>(tuw, trr, bur[0], brr[0], hrBh, hrBl);

    // ===== layer 2 (reads B buffers, gathers write A buffers) =====
    cudaStreamWaitEvent(s2, evGU1, 0);   // tru about to be overwritten; also huB needed
    wgemm2<<<gR, 256, GEMM_SMEM, s2>>>(hrBh, hrBl, wh + O_L[4], wl + O_L[4],
                                       tru, nullptr, nullptr, NR, H);
    cudaEventRecord(evT2, s2);
    cudaStreamWaitEvent(0, evT2, 0);
    gather_user<<<NU, 64>>>(tru, bru[1], huAh, huAl);
    cudaEventRecord(evGU2, 0);
    wgemm2<<<gU, 256, GEMM_SMEM, s2>>>(huBh, huBl, wh + O_L[3], wl + O_L[3],
                                       tuw, nullptr, nullptr, NU, H);
    wgemm2<<<gR, 256, GEMM_SMEM, s2>>>(hrBh, hrBl, wh + O_L[5], wl + O_L[5],
                                       trr, nullptr, nullptr, NR, H);
    gather_rest<<<NR, 64, 0, s2>>>(tuw, trr, bur[1], brr[1], hrAh, hrAl);

    // ===== output projections (parallel across streams) =====
    float* out = (float*)d_out;
    // stream0: user output (after its own gather_user L2, in-order)
    wgemm2<<<gU, 256, GEMM_SMEM>>>(huAh, huAl, wh + O_L[6], wl + O_L[6],
                                   out, nullptr, nullptr, NU, H);
    // s2: rest output (after gather_rest L2, in-order on s2)
    wgemm2<<<gR, 256, GEMM_SMEM, s2>>>(hrAh, hrAl, wh + O_L[7], wl + O_L[7],
                                       out + (size_t)NU * H, nullptr, nullptr, NR, H);
    cudaEventRecord(evJoin, s2);
    cudaStreamWaitEvent(0, evJoin, 0);
    (void)evGU2;
}